// round 10
// baseline (speedup 1.0000x reference)
#include <cuda_runtime.h>

#define NN 50000
#define EE 800000
#define ET 850000        // EE + NN self loops
#define FIN 128
#define D1 256           // H1*C1 = 4*64
#define C1C 64
#define NH1 4
#define D2 128
#define NG 32
#define NCLS 5
#define NEG_SLOPE 0.2f

// ---------------- scratch (static device globals) ---------------------------
__device__ float g_h1[(size_t)NN * D1];
__device__ float g_out1[(size_t)NN * D1];
__device__ float g_h2[(size_t)NN * D2];
__device__ float g_out2[(size_t)NN * D2];
__device__ float g_asrc1[NN * NH1], g_adst1[NN * NH1];
__device__ float g_asrc2[NN], g_adst2[NN];
__device__ float g_pool[NG * D2];
__device__ float g_cnt[NG];
// CSR by destination
__device__ int g_deg[NN];
__device__ int g_rowptr[NN + 1];
__device__ int g_cursor[NN];
__device__ int g_col[ET];

__device__ __forceinline__ float lrelu(float a) { return (a > 0.f) ? a : NEG_SLOPE * a; }
__device__ __forceinline__ float elu(float v)   { return (v > 0.f) ? v : expm1f(v); }

// ---------------- init ------------------------------------------------------
__global__ void init_kernel() {
    int i0 = blockIdx.x * blockDim.x + threadIdx.x;
    int stride = gridDim.x * blockDim.x;
    for (int i = i0; i < NN; i += stride) g_deg[i] = 0;
    for (int i = i0; i < NG * D2; i += stride) g_pool[i] = 0.f;
    if (i0 < NG) g_cnt[i0] = 0.f;
}

// ---------------- CSR build -------------------------------------------------
__global__ void deg_k(const int* __restrict__ ei) {
    int e = blockIdx.x * blockDim.x + threadIdx.x;
    if (e >= ET) return;
    int d = (e < EE) ? ei[EE + e] : (e - EE);
    atomicAdd(&g_deg[d], 1);
}

__global__ void scan_k() {
    const int T = 1024;
    const int CH = (NN + T - 1) / T;
    __shared__ int part[T];
    int t = threadIdx.x;
    int base = t * CH;
    int s = 0;
    for (int i = 0; i < CH; i++) {
        int idx = base + i;
        if (idx < NN) s += g_deg[idx];
    }
    part[t] = s;
    __syncthreads();
    for (int off = 1; off < T; off <<= 1) {
        int v = (t >= off) ? part[t - off] : 0;
        __syncthreads();
        part[t] += v;
        __syncthreads();
    }
    int run = part[t] - s;
    for (int i = 0; i < CH; i++) {
        int idx = base + i;
        if (idx < NN) {
            g_rowptr[idx] = run;
            g_cursor[idx] = run;
            run += g_deg[idx];
        }
    }
    if (t == 0) g_rowptr[NN] = ET;
}

__global__ void scatter_k(const int* __restrict__ ei) {
    int e = blockIdx.x * blockDim.x + threadIdx.x;
    if (e >= ET) return;
    int s, d;
    if (e < EE) { s = ei[e]; d = ei[EE + e]; }
    else        { s = e - EE; d = s; }
    int pos = atomicAdd(&g_cursor[d], 1);
    g_col[pos] = s;
}

// ---------------- GEMM (packed f32x2, TM=64, k-chunked) + fused scores -----
template <int KDIM, int NDIM, int TM, int HEADS>
__global__ void __launch_bounds__(NDIM, 512 / NDIM)
gemm_att_k(const float* __restrict__ X, const float* __restrict__ W,
           float* __restrict__ H,
           const float* __restrict__ att_s, const float* __restrict__ att_d,
           float* __restrict__ asrc, float* __restrict__ adst) {
    constexpr int KC = 128;                         // k-chunk resident in smem
    constexpr int STRIDE = TM + 4;
    constexpr int NWARP = NDIM / 32;
    __shared__ __align__(16) float xs[KC * STRIDE];
    __shared__ float part[NWARP * TM * 2];
    int row0 = blockIdx.x * TM;
    int tid = threadIdx.x;

    unsigned long long acc[TM / 2];
#pragma unroll
    for (int p = 0; p < TM / 2; p++) acc[p] = 0ull;

    for (int kc = 0; kc < KDIM; kc += KC) {
        if (kc) __syncthreads();
        for (int i = tid; i < TM * KC; i += NDIM) {
            int m = i / KC, k = i - m * KC;
            int r = row0 + m;
            xs[k * STRIDE + m] = (r < NN) ? X[(size_t)r * KDIM + kc + k] : 0.f;
        }
        __syncthreads();

        for (int k = 0; k < KC; k += 2) {
            float wa = W[(size_t)(kc + k) * NDIM + tid];
            float wb = W[(size_t)(kc + k + 1) * NDIM + tid];
            unsigned long long wpa, wpb;
            asm("mov.b64 %0, {%1, %1};" : "=l"(wpa) : "f"(wa));
            asm("mov.b64 %0, {%1, %1};" : "=l"(wpb) : "f"(wb));
            const ulonglong2* xa = reinterpret_cast<const ulonglong2*>(&xs[k * STRIDE]);
            const ulonglong2* xb = reinterpret_cast<const ulonglong2*>(&xs[(k + 1) * STRIDE]);
#pragma unroll
            for (int q = 0; q < TM / 4; q++) {
                ulonglong2 va = xa[q];
                asm("fma.rn.f32x2 %0, %1, %2, %0;" : "+l"(acc[2 * q])     : "l"(va.x), "l"(wpa));
                asm("fma.rn.f32x2 %0, %1, %2, %0;" : "+l"(acc[2 * q + 1]) : "l"(va.y), "l"(wpa));
            }
#pragma unroll
            for (int q = 0; q < TM / 4; q++) {
                ulonglong2 vb = xb[q];
                asm("fma.rn.f32x2 %0, %1, %2, %0;" : "+l"(acc[2 * q])     : "l"(vb.x), "l"(wpb));
                asm("fma.rn.f32x2 %0, %1, %2, %0;" : "+l"(acc[2 * q + 1]) : "l"(vb.y), "l"(wpb));
            }
        }
    }

    int lane = tid & 31, w = tid >> 5;
    float as = __ldg(&att_s[tid]);
    float ad = __ldg(&att_d[tid]);
#pragma unroll
    for (int p = 0; p < TM / 2; p++) {
        float lo, hi;
        asm("mov.b64 {%0, %1}, %2;" : "=f"(lo), "=f"(hi) : "l"(acc[p]));
        int r = row0 + 2 * p;
        if (r < NN)     H[(size_t)r * NDIM + tid] = lo;
        if (r + 1 < NN) H[(size_t)(r + 1) * NDIM + tid] = hi;
        float s0 = lo * as, d0 = lo * ad, s1 = hi * as, d1 = hi * ad;
#pragma unroll
        for (int o = 16; o; o >>= 1) {
            s0 += __shfl_xor_sync(0xffffffffu, s0, o);
            d0 += __shfl_xor_sync(0xffffffffu, d0, o);
            s1 += __shfl_xor_sync(0xffffffffu, s1, o);
            d1 += __shfl_xor_sync(0xffffffffu, d1, o);
        }
        if (!lane) {
            part[w * (TM * 2) + (2 * p) * 2 + 0] = s0;
            part[w * (TM * 2) + (2 * p) * 2 + 1] = d0;
            part[w * (TM * 2) + (2 * p + 1) * 2 + 0] = s1;
            part[w * (TM * 2) + (2 * p + 1) * 2 + 1] = d1;
        }
    }
    __syncthreads();
    constexpr int WPH = NWARP / HEADS;              // warps per head
    for (int t = tid; t < TM * HEADS * 2; t += NDIM) {
        int m = t % TM;
        int rest = t / TM;
        int h = rest % HEADS;
        int v = rest / HEADS;
        float sum = 0.f;
#pragma unroll
        for (int q = 0; q < WPH; q++) sum += part[(h * WPH + q) * (TM * 2) + m * 2 + v];
        int r = row0 + m;
        if (r < NN) {
            if (v == 0) asrc[r * HEADS + h] = sum;
            else        adst[r * HEADS + h] = sum;
        }
    }
}

// ---------------- fused softmax + aggregation ------------------------------
// layer1: TWO warps per dst node; each warp owns 128 channels (one head-pair)
// and runs a depth-3 pipelined gather.
__global__ void agg1_k(const float* __restrict__ bias) {
    int g = blockIdx.x * blockDim.x + threadIdx.x;
    int wg = g >> 5, lane = g & 31;
    if (wg >= 2 * NN) return;
    int d = wg >> 1, half = wg & 1;                 // half: channel block [0,128) or [128,256)
    int b = g_rowptr[d];
    int deg = g_rowptr[d + 1] - b;
    float2 adp = *reinterpret_cast<const float2*>(&g_adst1[d * NH1 + 2 * half]);

    float mxX = -1e30f, mxY = -1e30f;
    for (int i = lane; i < deg; i += 32) {
        int s = g_col[b + i];
        float2 a = *reinterpret_cast<const float2*>(&g_asrc1[s * NH1 + 2 * half]);
        mxX = fmaxf(mxX, lrelu(a.x + adp.x));
        mxY = fmaxf(mxY, lrelu(a.y + adp.y));
    }
#pragma unroll
    for (int o = 16; o; o >>= 1) {
        mxX = fmaxf(mxX, __shfl_xor_sync(0xffffffffu, mxX, o));
        mxY = fmaxf(mxY, __shfl_xor_sync(0xffffffffu, mxY, o));
    }

    int h0 = lane >> 4;                             // head within pair for my channels
    float adS = h0 ? adp.y : adp.x;
    float mxS = h0 ? mxY : mxX;
    int c4 = half * 32 + lane;                      // float4 index in the 256-ch row
    float den = 0.f;
    float4 acc = {0.f, 0.f, 0.f, 0.f};

    // depth-3 pipeline
    int sA = g_col[b];
    int sB = g_col[b + min(1, deg - 1)];
    float aA = g_asrc1[sA * NH1 + 2 * half + h0];
    float aB = g_asrc1[sB * NH1 + 2 * half + h0];
    float4 vA = reinterpret_cast<const float4*>(g_h1 + (size_t)sA * D1)[c4];
    float4 vB = reinterpret_cast<const float4*>(g_h1 + (size_t)sB * D1)[c4];
    for (int i = 0; i < deg; i++) {
        int j = min(i + 2, deg - 1);
        int sC = g_col[b + j];
        float aC = g_asrc1[sC * NH1 + 2 * half + h0];
        float4 vC = reinterpret_cast<const float4*>(g_h1 + (size_t)sC * D1)[c4];
        float e = __expf(lrelu(aA + adS) - mxS);
        den += e;
        acc.x = fmaf(vA.x, e, acc.x); acc.y = fmaf(vA.y, e, acc.y);
        acc.z = fmaf(vA.z, e, acc.z); acc.w = fmaf(vA.w, e, acc.w);
        aA = aB; vA = vB; aB = aC; vB = vC;
    }
    float inv = 1.f / (den + 1e-16f);
    float4 bb = __ldg(&reinterpret_cast<const float4*>(bias)[c4]);
    float4 o;
    o.x = elu(acc.x * inv + bb.x); o.y = elu(acc.y * inv + bb.y);
    o.z = elu(acc.z * inv + bb.z); o.w = elu(acc.w * inv + bb.w);
    reinterpret_cast<float4*>(g_out1 + (size_t)d * D1)[c4] = o;
}

// layer2: 1 head, 128 channels, one warp per dst, depth-3 pipeline
__global__ void agg2_k(const float* __restrict__ bias) {
    int g = blockIdx.x * blockDim.x + threadIdx.x;
    int d = g >> 5, lane = g & 31;
    if (d >= NN) return;
    int b = g_rowptr[d];
    int deg = g_rowptr[d + 1] - b;
    float ad = g_adst2[d];
    float mx = -1e30f;
    for (int i = lane; i < deg; i += 32) {
        int s = g_col[b + i];
        mx = fmaxf(mx, lrelu(g_asrc2[s] + ad));
    }
#pragma unroll
    for (int o = 16; o; o >>= 1) mx = fmaxf(mx, __shfl_xor_sync(0xffffffffu, mx, o));

    float den = 0.f;
    float4 acc = {0.f, 0.f, 0.f, 0.f};
    int sA = g_col[b];
    int sB = g_col[b + min(1, deg - 1)];
    float aA = g_asrc2[sA];
    float aB = g_asrc2[sB];
    float4 vA = reinterpret_cast<const float4*>(g_h2 + (size_t)sA * D2)[lane];
    float4 vB = reinterpret_cast<const float4*>(g_h2 + (size_t)sB * D2)[lane];
    for (int i = 0; i < deg; i++) {
        int j = min(i + 2, deg - 1);
        int sC = g_col[b + j];
        float aC = g_asrc2[sC];
        float4 vC = reinterpret_cast<const float4*>(g_h2 + (size_t)sC * D2)[lane];
        float e = __expf(lrelu(aA + ad) - mx);
        den += e;
        acc.x = fmaf(vA.x, e, acc.x); acc.y = fmaf(vA.y, e, acc.y);
        acc.z = fmaf(vA.z, e, acc.z); acc.w = fmaf(vA.w, e, acc.w);
        aA = aB; vA = vB; aB = aC; vB = vC;
    }
    float inv = 1.f / (den + 1e-16f);
    float4 bb = __ldg(&reinterpret_cast<const float4*>(bias)[lane]);
    float4 o;
    o.x = elu(acc.x * inv + bb.x); o.y = elu(acc.y * inv + bb.y);
    o.z = elu(acc.z * inv + bb.z); o.w = elu(acc.w * inv + bb.w);
    reinterpret_cast<float4*>(g_out2 + (size_t)d * D2)[lane] = o;
}

// ---------------- pooling (batch sorted -> segmented accumulation) ---------
#define NPB 128
__global__ void pool_k(const int* __restrict__ batch) {
    int c = threadIdx.x;
    int n0 = blockIdx.x * NPB;
    int n1 = min(NN, n0 + NPB);
    if (n0 >= NN) return;
    int curg = batch[n0];
    float acc = 0.f, cnt = 0.f;
    for (int n = n0; n < n1; n++) {
        int gg = batch[n];
        if (gg != curg) {
            atomicAdd(&g_pool[curg * D2 + c], acc);
            if (c == 0) atomicAdd(&g_cnt[curg], cnt);
            acc = 0.f; cnt = 0.f; curg = gg;
        }
        acc += g_out2[(size_t)n * D2 + c];
        cnt += 1.f;
    }
    atomicAdd(&g_pool[curg * D2 + c], acc);
    if (c == 0) atomicAdd(&g_cnt[curg], cnt);
}

__global__ void final_k(const float* __restrict__ lin_w, const float* __restrict__ lin_b,
                        float* __restrict__ out) {
    int t = threadIdx.x;
    if (t >= NG * NCLS) return;
    int gph = t / NCLS, k = t - gph * NCLS;
    float inv = 1.f / fmaxf(g_cnt[gph], 1.f);
    float acc = 0.f;
    for (int c = 0; c < D2; c++)
        acc = fmaf(g_pool[gph * D2 + c] * inv, __ldg(&lin_w[c * NCLS + k]), acc);
    out[t] = acc + lin_b[k];
}

// ---------------- driver -----------------------------------------------------
extern "C" void kernel_launch(void* const* d_in, const int* in_sizes, int n_in,
                              void* d_out, int out_size) {
    const float* x        = (const float*)d_in[0];
    const int*   ei       = (const int*)d_in[1];
    const int*   batch    = (const int*)d_in[2];
    const float* W1       = (const float*)d_in[3];
    const float* att_src1 = (const float*)d_in[4];
    const float* att_dst1 = (const float*)d_in[5];
    const float* b1       = (const float*)d_in[6];
    const float* W2       = (const float*)d_in[7];
    const float* att_src2 = (const float*)d_in[8];
    const float* att_dst2 = (const float*)d_in[9];
    const float* b2       = (const float*)d_in[10];
    const float* lin_w    = (const float*)d_in[11];
    const float* lin_b    = (const float*)d_in[12];
    float* out = (float*)d_out;

    static cudaStream_t s1 = 0;
    static cudaEvent_t evRoot = 0, evCsr = 0;
    static int inited = 0;
    if (!inited) {
        cudaStreamCreateWithFlags(&s1, cudaStreamNonBlocking);
        cudaEventCreateWithFlags(&evRoot, cudaEventDisableTiming);
        cudaEventCreateWithFlags(&evCsr, cudaEventDisableTiming);
        inited = 1;
    }

    float* h1p;    cudaGetSymbolAddress((void**)&h1p, g_h1);
    float* out1p;  cudaGetSymbolAddress((void**)&out1p, g_out1);
    float* h2p;    cudaGetSymbolAddress((void**)&h2p, g_h2);
    float* as1p;   cudaGetSymbolAddress((void**)&as1p, g_asrc1);
    float* ad1p;   cudaGetSymbolAddress((void**)&ad1p, g_adst1);
    float* as2p;   cudaGetSymbolAddress((void**)&as2p, g_asrc2);
    float* ad2p;   cudaGetSymbolAddress((void**)&ad2p, g_adst2);

    // fork: CSR build on s1, GEMM path on stream 0
    cudaEventRecord(evRoot, 0);
    cudaStreamWaitEvent(s1, evRoot, 0);
    init_kernel<<<256, 256, 0, s1>>>();
    deg_k<<<(ET + 255) / 256, 256, 0, s1>>>(ei);
    scan_k<<<1, 1024, 0, s1>>>();
    scatter_k<<<(ET + 255) / 256, 256, 0, s1>>>(ei);
    cudaEventRecord(evCsr, s1);

    gemm_att_k<FIN, D1, 64, NH1><<<(NN + 63) / 64, D1>>>(
        x, W1, h1p, att_src1, att_dst1, as1p, ad1p);

    // join: agg needs CSR
    cudaStreamWaitEvent(0, evCsr, 0);
    agg1_k<<<(2 * NN * 32 + 255) / 256, 256>>>(b1);

    gemm_att_k<D1, D2, 64, 1><<<(NN + 63) / 64, D2>>>(
        out1p, W2, h2p, att_src2, att_dst2, as2p, ad2p);
    agg2_k<<<(NN * 32 + 255) / 256, 256>>>(b2);

    pool_k<<<(NN + NPB - 1) / NPB, D2>>>(batch);
    final_k<<<1, 256>>>(lin_w, lin_b, out);
}

// round 11
// speedup vs baseline: 1.1423x; 1.1423x over previous
#include <cuda_runtime.h>
#include <cuda_fp16.h>

#define NN 50000
#define EE 800000
#define ET 850000        // EE + NN self loops
#define FIN 128
#define D1 256           // H1*C1 = 4*64
#define C1C 64
#define NH1 4
#define D2 128
#define NG 32
#define NCLS 5
#define NEG_SLOPE 0.2f

// ---------------- scratch (static device globals) ---------------------------
__device__ __half g_h1h[(size_t)NN * D1];    // layer1 features, fp16 (gather path)
__device__ float  g_out1[(size_t)NN * D1];
__device__ __half g_h2h[(size_t)NN * D2];    // layer2 features, fp16
__device__ float  g_out2[(size_t)NN * D2];
__device__ float  g_asrc1[NN * NH1], g_adst1[NN * NH1];
__device__ float  g_asrc2[NN], g_adst2[NN];
__device__ float  g_pool[NG * D2];
__device__ float  g_cnt[NG];
// CSR by destination
__device__ int g_deg[NN];
__device__ int g_rowptr[NN + 1];
__device__ int g_cursor[NN];
__device__ int g_col[ET];

__device__ __forceinline__ float lrelu(float a) { return (a > 0.f) ? a : NEG_SLOPE * a; }
__device__ __forceinline__ float elu(float v)   { return (v > 0.f) ? v : expm1f(v); }

// ---------------- init ------------------------------------------------------
__global__ void init_kernel() {
    int i0 = blockIdx.x * blockDim.x + threadIdx.x;
    int stride = gridDim.x * blockDim.x;
    for (int i = i0; i < NN; i += stride) g_deg[i] = 0;
    for (int i = i0; i < NG * D2; i += stride) g_pool[i] = 0.f;
    if (i0 < NG) g_cnt[i0] = 0.f;
}

// ---------------- CSR build -------------------------------------------------
__global__ void deg_k(const int* __restrict__ ei) {
    int e = blockIdx.x * blockDim.x + threadIdx.x;
    if (e >= ET) return;
    int d = (e < EE) ? ei[EE + e] : (e - EE);
    atomicAdd(&g_deg[d], 1);
}

__global__ void scan_k() {
    const int T = 1024;
    const int CH = (NN + T - 1) / T;
    __shared__ int part[T];
    int t = threadIdx.x;
    int base = t * CH;
    int s = 0;
    for (int i = 0; i < CH; i++) {
        int idx = base + i;
        if (idx < NN) s += g_deg[idx];
    }
    part[t] = s;
    __syncthreads();
    for (int off = 1; off < T; off <<= 1) {
        int v = (t >= off) ? part[t - off] : 0;
        __syncthreads();
        part[t] += v;
        __syncthreads();
    }
    int run = part[t] - s;
    for (int i = 0; i < CH; i++) {
        int idx = base + i;
        if (idx < NN) {
            g_rowptr[idx] = run;
            g_cursor[idx] = run;
            run += g_deg[idx];
        }
    }
    if (t == 0) g_rowptr[NN] = ET;
}

__global__ void scatter_k(const int* __restrict__ ei) {
    int e = blockIdx.x * blockDim.x + threadIdx.x;
    if (e >= ET) return;
    int s, d;
    if (e < EE) { s = ei[e]; d = ei[EE + e]; }
    else        { s = e - EE; d = s; }
    int pos = atomicAdd(&g_cursor[d], 1);
    g_col[pos] = s;
}

// ---------------- GEMM (packed f32x2, TM=32) + fused scores, fp16 output ---
template <int KDIM, int NDIM, int TM, int HEADS>
__global__ void gemm_att_k(const float* __restrict__ X, const float* __restrict__ W,
                           __half* __restrict__ H,
                           const float* __restrict__ att_s, const float* __restrict__ att_d,
                           float* __restrict__ asrc, float* __restrict__ adst) {
    constexpr int STRIDE = TM + 4;                  // 36 floats = 144B
    constexpr int NWARP = NDIM / 32;
    __shared__ __align__(16) float xs[KDIM * STRIDE];
    __shared__ float part[NWARP * TM * 2];
    int row0 = blockIdx.x * TM;
    int tid = threadIdx.x;                          // NDIM threads
    for (int i = tid; i < TM * KDIM; i += NDIM) {
        int m = i / KDIM, k = i - m * KDIM;
        int r = row0 + m;
        xs[k * STRIDE + m] = (r < NN) ? X[(size_t)r * KDIM + k] : 0.f;
    }
    __syncthreads();

    unsigned long long acc[TM / 2];
#pragma unroll
    for (int p = 0; p < TM / 2; p++) acc[p] = 0ull;

    for (int k = 0; k < KDIM; k += 2) {
        float wa = W[(size_t)k * NDIM + tid];
        float wb = W[(size_t)(k + 1) * NDIM + tid];
        unsigned long long wpa, wpb;
        asm("mov.b64 %0, {%1, %1};" : "=l"(wpa) : "f"(wa));
        asm("mov.b64 %0, {%1, %1};" : "=l"(wpb) : "f"(wb));
        const ulonglong2* xa = reinterpret_cast<const ulonglong2*>(&xs[k * STRIDE]);
        const ulonglong2* xb = reinterpret_cast<const ulonglong2*>(&xs[(k + 1) * STRIDE]);
#pragma unroll
        for (int q = 0; q < TM / 4; q++) {
            ulonglong2 va = xa[q];
            asm("fma.rn.f32x2 %0, %1, %2, %0;" : "+l"(acc[2 * q])     : "l"(va.x), "l"(wpa));
            asm("fma.rn.f32x2 %0, %1, %2, %0;" : "+l"(acc[2 * q + 1]) : "l"(va.y), "l"(wpa));
        }
#pragma unroll
        for (int q = 0; q < TM / 4; q++) {
            ulonglong2 vb = xb[q];
            asm("fma.rn.f32x2 %0, %1, %2, %0;" : "+l"(acc[2 * q])     : "l"(vb.x), "l"(wpb));
            asm("fma.rn.f32x2 %0, %1, %2, %0;" : "+l"(acc[2 * q + 1]) : "l"(vb.y), "l"(wpb));
        }
    }

    int lane = tid & 31, w = tid >> 5;
    float as = __ldg(&att_s[tid]);
    float ad = __ldg(&att_d[tid]);
#pragma unroll
    for (int p = 0; p < TM / 2; p++) {
        float lo, hi;
        asm("mov.b64 {%0, %1}, %2;" : "=f"(lo), "=f"(hi) : "l"(acc[p]));
        int r = row0 + 2 * p;
        if (r < NN)     H[(size_t)r * NDIM + tid] = __float2half(lo);
        if (r + 1 < NN) H[(size_t)(r + 1) * NDIM + tid] = __float2half(hi);
        float s0 = lo * as, d0 = lo * ad, s1 = hi * as, d1 = hi * ad;
#pragma unroll
        for (int o = 16; o; o >>= 1) {
            s0 += __shfl_xor_sync(0xffffffffu, s0, o);
            d0 += __shfl_xor_sync(0xffffffffu, d0, o);
            s1 += __shfl_xor_sync(0xffffffffu, s1, o);
            d1 += __shfl_xor_sync(0xffffffffu, d1, o);
        }
        if (!lane) {
            part[w * (TM * 2) + (2 * p) * 2 + 0] = s0;
            part[w * (TM * 2) + (2 * p) * 2 + 1] = d0;
            part[w * (TM * 2) + (2 * p + 1) * 2 + 0] = s1;
            part[w * (TM * 2) + (2 * p + 1) * 2 + 1] = d1;
        }
    }
    __syncthreads();
    constexpr int WPH = NWARP / HEADS;              // warps per head
    if (tid < TM * HEADS * 2) {
        int m = tid % TM;
        int rest = tid / TM;
        int h = rest % HEADS;
        int v = rest / HEADS;
        float sum = 0.f;
#pragma unroll
        for (int q = 0; q < WPH; q++) sum += part[(h * WPH + q) * (TM * 2) + m * 2 + v];
        int r = row0 + m;
        if (r < NN) {
            if (v == 0) asrc[r * HEADS + h] = sum;
            else        adst[r * HEADS + h] = sum;
        }
    }
}

// ---------------- fused softmax + aggregation (warp per dst, fp16 gather) --
// layer1: 4 heads, 256 channels. lane owns channels [8*lane, 8*lane+8),
// which all lie in head lane>>3. One 16B load per edge per lane.
__global__ void agg1_k(const float* __restrict__ bias) {
    int g = blockIdx.x * blockDim.x + threadIdx.x;
    int d = g >> 5, lane = g & 31;
    if (d >= NN) return;
    int b = g_rowptr[d];
    int deg = g_rowptr[d + 1] - b;
    float ad0 = g_adst1[d * NH1 + 0], ad1 = g_adst1[d * NH1 + 1];
    float ad2 = g_adst1[d * NH1 + 2], ad3 = g_adst1[d * NH1 + 3];

    float mx0 = -1e30f, mx1 = -1e30f, mx2 = -1e30f, mx3 = -1e30f;
    for (int i = lane; i < deg; i += 32) {
        int s = g_col[b + i];
        float4 a = *reinterpret_cast<const float4*>(&g_asrc1[s * NH1]);
        mx0 = fmaxf(mx0, lrelu(a.x + ad0));
        mx1 = fmaxf(mx1, lrelu(a.y + ad1));
        mx2 = fmaxf(mx2, lrelu(a.z + ad2));
        mx3 = fmaxf(mx3, lrelu(a.w + ad3));
    }
#pragma unroll
    for (int o = 16; o; o >>= 1) {
        mx0 = fmaxf(mx0, __shfl_xor_sync(0xffffffffu, mx0, o));
        mx1 = fmaxf(mx1, __shfl_xor_sync(0xffffffffu, mx1, o));
        mx2 = fmaxf(mx2, __shfl_xor_sync(0xffffffffu, mx2, o));
        mx3 = fmaxf(mx3, __shfl_xor_sync(0xffffffffu, mx3, o));
    }

    int h = lane >> 3;                              // my head (0..3)
    float adS = (h == 0) ? ad0 : (h == 1) ? ad1 : (h == 2) ? ad2 : ad3;
    float mxS = (h == 0) ? mx0 : (h == 1) ? mx1 : (h == 2) ? mx2 : mx3;
    float den = 0.f;
    float acc[8];
#pragma unroll
    for (int q = 0; q < 8; q++) acc[q] = 0.f;

    // depth-2 software pipeline
    int sA = g_col[b];
    float aA = g_asrc1[sA * NH1 + h];
    uint4 vA = *reinterpret_cast<const uint4*>(&g_h1h[(size_t)sA * D1 + lane * 8]);
    for (int i = 0; i < deg; i++) {
        int j = min(i + 1, deg - 1);
        int sN = g_col[b + j];
        float aN = g_asrc1[sN * NH1 + h];
        uint4 vN = *reinterpret_cast<const uint4*>(&g_h1h[(size_t)sN * D1 + lane * 8]);
        float e = __expf(lrelu(aA + adS) - mxS);
        den += e;
        const __half2* hp = reinterpret_cast<const __half2*>(&vA);
#pragma unroll
        for (int q = 0; q < 4; q++) {
            float2 f = __half22float2(hp[q]);
            acc[2 * q]     = fmaf(f.x, e, acc[2 * q]);
            acc[2 * q + 1] = fmaf(f.y, e, acc[2 * q + 1]);
        }
        aA = aN; vA = vN;
    }
    float inv = 1.f / (den + 1e-16f);
    float4 b0 = __ldg(&reinterpret_cast<const float4*>(bias)[2 * lane]);
    float4 b1 = __ldg(&reinterpret_cast<const float4*>(bias)[2 * lane + 1]);
    float4 o0, o1;
    o0.x = elu(acc[0] * inv + b0.x); o0.y = elu(acc[1] * inv + b0.y);
    o0.z = elu(acc[2] * inv + b0.z); o0.w = elu(acc[3] * inv + b0.w);
    o1.x = elu(acc[4] * inv + b1.x); o1.y = elu(acc[5] * inv + b1.y);
    o1.z = elu(acc[6] * inv + b1.z); o1.w = elu(acc[7] * inv + b1.w);
    float4* op = reinterpret_cast<float4*>(g_out1 + (size_t)d * D1);
    op[2 * lane] = o0;
    op[2 * lane + 1] = o1;
}

// layer2: 1 head, 128 channels; lane owns 4 channels (8B load per edge)
__global__ void agg2_k(const float* __restrict__ bias) {
    int g = blockIdx.x * blockDim.x + threadIdx.x;
    int d = g >> 5, lane = g & 31;
    if (d >= NN) return;
    int b = g_rowptr[d];
    int deg = g_rowptr[d + 1] - b;
    float ad = g_adst2[d];
    float mx = -1e30f;
    for (int i = lane; i < deg; i += 32) {
        int s = g_col[b + i];
        mx = fmaxf(mx, lrelu(g_asrc2[s] + ad));
    }
#pragma unroll
    for (int o = 16; o; o >>= 1) mx = fmaxf(mx, __shfl_xor_sync(0xffffffffu, mx, o));

    float den = 0.f;
    float acc[4];
#pragma unroll
    for (int q = 0; q < 4; q++) acc[q] = 0.f;

    int sA = g_col[b];
    float aA = g_asrc2[sA];
    uint2 vA = *reinterpret_cast<const uint2*>(&g_h2h[(size_t)sA * D2 + lane * 4]);
    for (int i = 0; i < deg; i++) {
        int j = min(i + 1, deg - 1);
        int sN = g_col[b + j];
        float aN = g_asrc2[sN];
        uint2 vN = *reinterpret_cast<const uint2*>(&g_h2h[(size_t)sN * D2 + lane * 4]);
        float e = __expf(lrelu(aA + ad) - mx);
        den += e;
        const __half2* hp = reinterpret_cast<const __half2*>(&vA);
#pragma unroll
        for (int q = 0; q < 2; q++) {
            float2 f = __half22float2(hp[q]);
            acc[2 * q]     = fmaf(f.x, e, acc[2 * q]);
            acc[2 * q + 1] = fmaf(f.y, e, acc[2 * q + 1]);
        }
        aA = aN; vA = vN;
    }
    float inv = 1.f / (den + 1e-16f);
    float4 bb = __ldg(&reinterpret_cast<const float4*>(bias)[lane]);
    float4 o;
    o.x = elu(acc[0] * inv + bb.x); o.y = elu(acc[1] * inv + bb.y);
    o.z = elu(acc[2] * inv + bb.z); o.w = elu(acc[3] * inv + bb.w);
    reinterpret_cast<float4*>(g_out2 + (size_t)d * D2)[lane] = o;
}

// ---------------- pooling (batch sorted -> segmented accumulation) ---------
#define NPB 128
__global__ void pool_k(const int* __restrict__ batch) {
    int c = threadIdx.x;
    int n0 = blockIdx.x * NPB;
    int n1 = min(NN, n0 + NPB);
    if (n0 >= NN) return;
    int curg = batch[n0];
    float acc = 0.f, cnt = 0.f;
    for (int n = n0; n < n1; n++) {
        int gg = batch[n];
        if (gg != curg) {
            atomicAdd(&g_pool[curg * D2 + c], acc);
            if (c == 0) atomicAdd(&g_cnt[curg], cnt);
            acc = 0.f; cnt = 0.f; curg = gg;
        }
        acc += g_out2[(size_t)n * D2 + c];
        cnt += 1.f;
    }
    atomicAdd(&g_pool[curg * D2 + c], acc);
    if (c == 0) atomicAdd(&g_cnt[curg], cnt);
}

__global__ void final_k(const float* __restrict__ lin_w, const float* __restrict__ lin_b,
                        float* __restrict__ out) {
    int t = threadIdx.x;
    if (t >= NG * NCLS) return;
    int gph = t / NCLS, k = t - gph * NCLS;
    float inv = 1.f / fmaxf(g_cnt[gph], 1.f);
    float acc = 0.f;
    for (int c = 0; c < D2; c++)
        acc = fmaf(g_pool[gph * D2 + c] * inv, __ldg(&lin_w[c * NCLS + k]), acc);
    out[t] = acc + lin_b[k];
}

// ---------------- driver -----------------------------------------------------
extern "C" void kernel_launch(void* const* d_in, const int* in_sizes, int n_in,
                              void* d_out, int out_size) {
    const float* x        = (const float*)d_in[0];
    const int*   ei       = (const int*)d_in[1];
    const int*   batch    = (const int*)d_in[2];
    const float* W1       = (const float*)d_in[3];
    const float* att_src1 = (const float*)d_in[4];
    const float* att_dst1 = (const float*)d_in[5];
    const float* b1       = (const float*)d_in[6];
    const float* W2       = (const float*)d_in[7];
    const float* att_src2 = (const float*)d_in[8];
    const float* att_dst2 = (const float*)d_in[9];
    const float* b2       = (const float*)d_in[10];
    const float* lin_w    = (const float*)d_in[11];
    const float* lin_b    = (const float*)d_in[12];
    float* out = (float*)d_out;

    static cudaStream_t s1 = 0;
    static cudaEvent_t evRoot = 0, evCsr = 0;
    static int inited = 0;
    if (!inited) {
        cudaStreamCreateWithFlags(&s1, cudaStreamNonBlocking);
        cudaEventCreateWithFlags(&evRoot, cudaEventDisableTiming);
        cudaEventCreateWithFlags(&evCsr, cudaEventDisableTiming);
        inited = 1;
    }

    __half* h1p;   cudaGetSymbolAddress((void**)&h1p, g_h1h);
    float*  out1p; cudaGetSymbolAddress((void**)&out1p, g_out1);
    __half* h2p;   cudaGetSymbolAddress((void**)&h2p, g_h2h);
    float*  as1p;  cudaGetSymbolAddress((void**)&as1p, g_asrc1);
    float*  ad1p;  cudaGetSymbolAddress((void**)&ad1p, g_adst1);
    float*  as2p;  cudaGetSymbolAddress((void**)&as2p, g_asrc2);
    float*  ad2p;  cudaGetSymbolAddress((void**)&ad2p, g_adst2);

    // fork: CSR build on s1, GEMM path on stream 0
    cudaEventRecord(evRoot, 0);
    cudaStreamWaitEvent(s1, evRoot, 0);
    init_kernel<<<256, 256, 0, s1>>>();
    deg_k<<<(ET + 255) / 256, 256, 0, s1>>>(ei);
    scan_k<<<1, 1024, 0, s1>>>();
    scatter_k<<<(ET + 255) / 256, 256, 0, s1>>>(ei);
    cudaEventRecord(evCsr, s1);

    gemm_att_k<FIN, D1, 32, NH1><<<(NN + 31) / 32, D1>>>(
        x, W1, h1p, att_src1, att_dst1, as1p, ad1p);

    // join: agg needs CSR
    cudaStreamWaitEvent(0, evCsr, 0);
    agg1_k<<<(NN * 32 + 255) / 256, 256>>>(b1);

    gemm_att_k<D1, D2, 32, 1><<<(NN + 31) / 32, D2>>>(
        out1p, W2, h2p, att_src2, att_dst2, as2p, ad2p);
    agg2_k<<<(NN * 32 + 255) / 256, 256>>>(b2);

    pool_k<<<(NN + NPB - 1) / NPB, D2>>>(batch);
    final_k<<<1, 256>>>(lin_w, lin_b, out);
}

// round 12
// speedup vs baseline: 1.7206x; 1.5062x over previous
#include <cuda_runtime.h>
#include <cuda_fp16.h>

#define NN 50000
#define EE 800000
#define ET 850000        // EE + NN self loops
#define FIN 128
#define D1 256           // H1*C1 = 4*64
#define C1C 64
#define NH1 4
#define D2 128
#define NG 32
#define NCLS 5
#define NEG_SLOPE 0.2f

// ---------------- scratch (static device globals) ---------------------------
__device__ __half g_h1h[(size_t)NN * D1];    // layer1 features, fp16 (gather path)
__device__ __half g_out1h[(size_t)NN * D1];  // elu(agg)+bias of layer1, fp16 (GEMM2 input)
__device__ __half g_h2h[(size_t)NN * D2];    // layer2 features, fp16
__device__ float  g_out2[(size_t)NN * D2];
__device__ __half g_w1h[FIN * D1];
__device__ __half g_w2h[D1 * D2];
__device__ float  g_asrc1[NN * NH1], g_adst1[NN * NH1];
__device__ float  g_asrc2[NN], g_adst2[NN];
__device__ float  g_pool[NG * D2];
__device__ float  g_cnt[NG];
// CSR by destination
__device__ int g_deg[NN];
__device__ int g_rowptr[NN + 1];
__device__ int g_cursor[NN];
__device__ int g_col[ET];

__device__ __forceinline__ float lrelu(float a) { return (a > 0.f) ? a : NEG_SLOPE * a; }
__device__ __forceinline__ float elu(float v)   { return (v > 0.f) ? v : expm1f(v); }
__device__ __forceinline__ unsigned sptr(const void* p) {
    return (unsigned)__cvta_generic_to_shared(p);
}

// ---------------- init ------------------------------------------------------
__global__ void init_kernel() {
    int i0 = blockIdx.x * blockDim.x + threadIdx.x;
    int stride = gridDim.x * blockDim.x;
    for (int i = i0; i < NN; i += stride) g_deg[i] = 0;
    for (int i = i0; i < NG * D2; i += stride) g_pool[i] = 0.f;
    if (i0 < NG) g_cnt[i0] = 0.f;
}

// ---------------- W conversion to fp16 --------------------------------------
__global__ void convw_k(const float* __restrict__ W1, const float* __restrict__ W2) {
    int i = blockIdx.x * blockDim.x + threadIdx.x;   // 32768 of each
    if (i < FIN * D1) g_w1h[i] = __float2half(W1[i]);
    if (i < D1 * D2)  g_w2h[i] = __float2half(W2[i]);
}

// ---------------- CSR build -------------------------------------------------
__global__ void deg_k(const int* __restrict__ ei) {
    int e = blockIdx.x * blockDim.x + threadIdx.x;
    if (e >= ET) return;
    int d = (e < EE) ? ei[EE + e] : (e - EE);
    atomicAdd(&g_deg[d], 1);
}

__global__ void scan_k() {
    const int T = 1024;
    const int CH = (NN + T - 1) / T;
    __shared__ int part[T];
    int t = threadIdx.x;
    int base = t * CH;
    int s = 0;
    for (int i = 0; i < CH; i++) {
        int idx = base + i;
        if (idx < NN) s += g_deg[idx];
    }
    part[t] = s;
    __syncthreads();
    for (int off = 1; off < T; off <<= 1) {
        int v = (t >= off) ? part[t - off] : 0;
        __syncthreads();
        part[t] += v;
        __syncthreads();
    }
    int run = part[t] - s;
    for (int i = 0; i < CH; i++) {
        int idx = base + i;
        if (idx < NN) {
            g_rowptr[idx] = run;
            g_cursor[idx] = run;
            run += g_deg[idx];
        }
    }
    if (t == 0) g_rowptr[NN] = ET;
}

__global__ void scatter_k(const int* __restrict__ ei) {
    int e = blockIdx.x * blockDim.x + threadIdx.x;
    if (e >= ET) return;
    int s, d;
    if (e < EE) { s = ei[e]; d = ei[EE + e]; }
    else        { s = e - EE; d = s; }
    int pos = atomicAdd(&g_cursor[d], 1);
    g_col[pos] = s;
}

// ---------------- tensor-core GEMM + fused attention scores ----------------
// H[r,n] = sum_k A[r,k] * W[k,n] (fp16 in, fp32 accum, fp16 out)
// asrc[r,h] = sum_n H[r,n]*att_s[n] over head h's span; adst likewise.
// A source: fp32 (layer1: x) or fp16 (layer2: out1h), selected by A_FP16.
template <int KDIM, int NDIM, int MBLK, int MW, int NW, int HEADS, bool A_FP16>
__global__ void __launch_bounds__(MW * NW * 32)
gemm_tc_k(const void* __restrict__ Ain, const __half* __restrict__ Wh,
          __half* __restrict__ H,
          const float* __restrict__ att_s, const float* __restrict__ att_d,
          float* __restrict__ asrc, float* __restrict__ adst) {
    constexpr int AST = KDIM + 8;                   // A smem row stride (halves)
    constexpr int WST = NDIM + 8;                   // W smem row stride (halves)
    constexpr int NTHR = MW * NW * 32;
    constexpr int NWP = NDIM / NW;                  // cols per warp
    constexpr int NFRAG = NWP / 8;
    constexpr int SPAN = NDIM / HEADS;              // cols per head
    constexpr int JPH = SPAN / 8;                   // n-frags per head
    constexpr int HSLOTS = NWP / SPAN > 0 ? NWP / SPAN : 1;
    extern __shared__ __align__(16) __half smem[];
    __half* As = smem;                              // [MBLK][AST]
    __half* Ws = smem + MBLK * AST;                 // [KDIM][WST]
    int tid = threadIdx.x;
    int row0 = blockIdx.x * MBLK;

    // stage A (convert fp32->fp16 if needed)
    for (int idx = tid; idx < MBLK * (KDIM / 8); idx += NTHR) {
        int m = idx / (KDIM / 8), kc = (idx % (KDIM / 8)) * 8;
        int r = row0 + m;
        uint4 pack = {0u, 0u, 0u, 0u};
        if (r < NN) {
            if (A_FP16) {
                pack = *reinterpret_cast<const uint4*>(
                    reinterpret_cast<const __half*>(Ain) + (size_t)r * KDIM + kc);
            } else {
                const float4* xp = reinterpret_cast<const float4*>(
                    reinterpret_cast<const float*>(Ain) + (size_t)r * KDIM + kc);
                float4 f0 = xp[0], f1 = xp[1];
                __half2 h0 = __floats2half2_rn(f0.x, f0.y);
                __half2 h1 = __floats2half2_rn(f0.z, f0.w);
                __half2 h2 = __floats2half2_rn(f1.x, f1.y);
                __half2 h3 = __floats2half2_rn(f1.z, f1.w);
                pack.x = *reinterpret_cast<unsigned*>(&h0);
                pack.y = *reinterpret_cast<unsigned*>(&h1);
                pack.z = *reinterpret_cast<unsigned*>(&h2);
                pack.w = *reinterpret_cast<unsigned*>(&h3);
            }
        }
        *reinterpret_cast<uint4*>(&As[m * AST + kc]) = pack;
    }
    // stage W (already fp16)
    for (int idx = tid; idx < KDIM * (NDIM / 8); idx += NTHR) {
        int k = idx / (NDIM / 8), nc = (idx % (NDIM / 8)) * 8;
        *reinterpret_cast<uint4*>(&Ws[k * WST + nc]) =
            *reinterpret_cast<const uint4*>(&Wh[(size_t)k * NDIM + nc]);
    }
    __syncthreads();

    int wid = tid >> 5, lane = tid & 31;
    int wm = wid % MW, wn = wid / MW;
    int mb = wm * 16, nb = wn * NWP;

    float acc[NFRAG][4];
#pragma unroll
    for (int j = 0; j < NFRAG; j++)
#pragma unroll
        for (int q = 0; q < 4; q++) acc[j][q] = 0.f;

    for (int k0 = 0; k0 < KDIM; k0 += 16) {
        unsigned a0, a1, a2, a3;
        unsigned aaddr = sptr(&As[(mb + (lane & 15)) * AST + k0 + (lane >> 4) * 8]);
        asm volatile("ldmatrix.sync.aligned.m8n8.x4.shared.b16 {%0,%1,%2,%3}, [%4];"
                     : "=r"(a0), "=r"(a1), "=r"(a2), "=r"(a3) : "r"(aaddr));
#pragma unroll
        for (int j = 0; j < NFRAG; j++) {
            unsigned b0, b1;
            unsigned baddr = sptr(&Ws[(k0 + (lane & 15)) * WST + nb + j * 8]);
            asm volatile("ldmatrix.sync.aligned.m8n8.x2.trans.shared.b16 {%0,%1}, [%2];"
                         : "=r"(b0), "=r"(b1) : "r"(baddr));
            asm volatile("mma.sync.aligned.m16n8k16.row.col.f32.f16.f16.f32 "
                         "{%0,%1,%2,%3}, {%4,%5,%6,%7}, {%8,%9}, {%0,%1,%2,%3};"
                         : "+f"(acc[j][0]), "+f"(acc[j][1]), "+f"(acc[j][2]), "+f"(acc[j][3])
                         : "r"(a0), "r"(a1), "r"(a2), "r"(a3), "r"(b0), "r"(b1));
        }
    }

    // epilogue: store H (fp16) + fused score dots
    float sS[2][HSLOTS], sD[2][HSLOTS];
#pragma unroll
    for (int r = 0; r < 2; r++)
#pragma unroll
        for (int hs = 0; hs < HSLOTS; hs++) { sS[r][hs] = 0.f; sD[r][hs] = 0.f; }
    int rg0 = row0 + mb + (lane >> 2);              // rows rg0, rg0+8
#pragma unroll
    for (int j = 0; j < NFRAG; j++) {
        int c0 = nb + j * 8 + (lane & 3) * 2;
        float as0 = __ldg(&att_s[c0]), as1 = __ldg(&att_s[c0 + 1]);
        float ad0 = __ldg(&att_d[c0]), ad1 = __ldg(&att_d[c0 + 1]);
        int slot = j / JPH;
        sS[0][slot] += acc[j][0] * as0 + acc[j][1] * as1;
        sS[1][slot] += acc[j][2] * as0 + acc[j][3] * as1;
        sD[0][slot] += acc[j][0] * ad0 + acc[j][1] * ad1;
        sD[1][slot] += acc[j][2] * ad0 + acc[j][3] * ad1;
        if (rg0 < NN) {
            __half2 hv = __floats2half2_rn(acc[j][0], acc[j][1]);
            *reinterpret_cast<__half2*>(&H[(size_t)rg0 * NDIM + c0]) = hv;
        }
        if (rg0 + 8 < NN) {
            __half2 hv = __floats2half2_rn(acc[j][2], acc[j][3]);
            *reinterpret_cast<__half2*>(&H[(size_t)(rg0 + 8) * NDIM + c0]) = hv;
        }
    }
#pragma unroll
    for (int r = 0; r < 2; r++)
#pragma unroll
        for (int hs = 0; hs < HSLOTS; hs++) {
            sS[r][hs] += __shfl_xor_sync(0xffffffffu, sS[r][hs], 1);
            sS[r][hs] += __shfl_xor_sync(0xffffffffu, sS[r][hs], 2);
            sD[r][hs] += __shfl_xor_sync(0xffffffffu, sD[r][hs], 1);
            sD[r][hs] += __shfl_xor_sync(0xffffffffu, sD[r][hs], 2);
        }
    if ((lane & 3) == 0) {
        int hbase = nb / SPAN;
#pragma unroll
        for (int hs = 0; hs < HSLOTS; hs++) {
            int h = hbase + hs;
            if (rg0 < NN) {
                asrc[rg0 * HEADS + h] = sS[0][hs];
                adst[rg0 * HEADS + h] = sD[0][hs];
            }
            if (rg0 + 8 < NN) {
                asrc[(rg0 + 8) * HEADS + h] = sS[1][hs];
                adst[(rg0 + 8) * HEADS + h] = sD[1][hs];
            }
        }
    }
}

// ---------------- fused softmax + aggregation (warp per dst, fp16 gather) --
// layer1: 4 heads, 256 channels. lane owns channels [8*lane, 8*lane+8) in head lane>>3.
__global__ void agg1_k(const float* __restrict__ bias) {
    int g = blockIdx.x * blockDim.x + threadIdx.x;
    int d = g >> 5, lane = g & 31;
    if (d >= NN) return;
    int b = g_rowptr[d];
    int deg = g_rowptr[d + 1] - b;
    float ad0 = g_adst1[d * NH1 + 0], ad1 = g_adst1[d * NH1 + 1];
    float ad2 = g_adst1[d * NH1 + 2], ad3 = g_adst1[d * NH1 + 3];

    float mx0 = -1e30f, mx1 = -1e30f, mx2 = -1e30f, mx3 = -1e30f;
    for (int i = lane; i < deg; i += 32) {
        int s = g_col[b + i];
        float4 a = *reinterpret_cast<const float4*>(&g_asrc1[s * NH1]);
        mx0 = fmaxf(mx0, lrelu(a.x + ad0));
        mx1 = fmaxf(mx1, lrelu(a.y + ad1));
        mx2 = fmaxf(mx2, lrelu(a.z + ad2));
        mx3 = fmaxf(mx3, lrelu(a.w + ad3));
    }
#pragma unroll
    for (int o = 16; o; o >>= 1) {
        mx0 = fmaxf(mx0, __shfl_xor_sync(0xffffffffu, mx0, o));
        mx1 = fmaxf(mx1, __shfl_xor_sync(0xffffffffu, mx1, o));
        mx2 = fmaxf(mx2, __shfl_xor_sync(0xffffffffu, mx2, o));
        mx3 = fmaxf(mx3, __shfl_xor_sync(0xffffffffu, mx3, o));
    }

    int h = lane >> 3;
    float adS = (h == 0) ? ad0 : (h == 1) ? ad1 : (h == 2) ? ad2 : ad3;
    float mxS = (h == 0) ? mx0 : (h == 1) ? mx1 : (h == 2) ? mx2 : mx3;
    float den = 0.f;
    float acc[8];
#pragma unroll
    for (int q = 0; q < 8; q++) acc[q] = 0.f;

    int sA = g_col[b];
    float aA = g_asrc1[sA * NH1 + h];
    uint4 vA = *reinterpret_cast<const uint4*>(&g_h1h[(size_t)sA * D1 + lane * 8]);
    for (int i = 0; i < deg; i++) {
        int j = min(i + 1, deg - 1);
        int sN = g_col[b + j];
        float aN = g_asrc1[sN * NH1 + h];
        uint4 vN = *reinterpret_cast<const uint4*>(&g_h1h[(size_t)sN * D1 + lane * 8]);
        float e = __expf(lrelu(aA + adS) - mxS);
        den += e;
        const __half2* hp = reinterpret_cast<const __half2*>(&vA);
#pragma unroll
        for (int q = 0; q < 4; q++) {
            float2 f = __half22float2(hp[q]);
            acc[2 * q]     = fmaf(f.x, e, acc[2 * q]);
            acc[2 * q + 1] = fmaf(f.y, e, acc[2 * q + 1]);
        }
        aA = aN; vA = vN;
    }
    float inv = 1.f / (den + 1e-16f);
    float4 b0 = __ldg(&reinterpret_cast<const float4*>(bias)[2 * lane]);
    float4 b1 = __ldg(&reinterpret_cast<const float4*>(bias)[2 * lane + 1]);
    float o0 = elu(acc[0] * inv + b0.x), o1 = elu(acc[1] * inv + b0.y);
    float o2 = elu(acc[2] * inv + b0.z), o3 = elu(acc[3] * inv + b0.w);
    float o4 = elu(acc[4] * inv + b1.x), o5 = elu(acc[5] * inv + b1.y);
    float o6 = elu(acc[6] * inv + b1.z), o7 = elu(acc[7] * inv + b1.w);
    __half2 p0 = __floats2half2_rn(o0, o1), p1 = __floats2half2_rn(o2, o3);
    __half2 p2 = __floats2half2_rn(o4, o5), p3 = __floats2half2_rn(o6, o7);
    uint4 pack;
    pack.x = *reinterpret_cast<unsigned*>(&p0);
    pack.y = *reinterpret_cast<unsigned*>(&p1);
    pack.z = *reinterpret_cast<unsigned*>(&p2);
    pack.w = *reinterpret_cast<unsigned*>(&p3);
    *reinterpret_cast<uint4*>(&g_out1h[(size_t)d * D1 + lane * 8]) = pack;
}

// layer2: 1 head, 128 channels; lane owns 4 channels
__global__ void agg2_k(const float* __restrict__ bias) {
    int g = blockIdx.x * blockDim.x + threadIdx.x;
    int d = g >> 5, lane = g & 31;
    if (d >= NN) return;
    int b = g_rowptr[d];
    int deg = g_rowptr[d + 1] - b;
    float ad = g_adst2[d];
    float mx = -1e30f;
    for (int i = lane; i < deg; i += 32) {
        int s = g_col[b + i];
        mx = fmaxf(mx, lrelu(g_asrc2[s] + ad));
    }
#pragma unroll
    for (int o = 16; o; o >>= 1) mx = fmaxf(mx, __shfl_xor_sync(0xffffffffu, mx, o));

    float den = 0.f;
    float acc[4];
#pragma unroll
    for (int q = 0; q < 4; q++) acc[q] = 0.f;

    int sA = g_col[b];
    float aA = g_asrc2[sA];
    uint2 vA = *reinterpret_cast<const uint2*>(&g_h2h[(size_t)sA * D2 + lane * 4]);
    for (int i = 0; i < deg; i++) {
        int j = min(i + 1, deg - 1);
        int sN = g_col[b + j];
        float aN = g_asrc2[sN];
        uint2 vN = *reinterpret_cast<const uint2*>(&g_h2h[(size_t)sN * D2 + lane * 4]);
        float e = __expf(lrelu(aA + ad) - mx);
        den += e;
        const __half2* hp = reinterpret_cast<const __half2*>(&vA);
#pragma unroll
        for (int q = 0; q < 2; q++) {
            float2 f = __half22float2(hp[q]);
            acc[2 * q]     = fmaf(f.x, e, acc[2 * q]);
            acc[2 * q + 1] = fmaf(f.y, e, acc[2 * q + 1]);
        }
        aA = aN; vA = vN;
    }
    float inv = 1.f / (den + 1e-16f);
    float4 bb = __ldg(&reinterpret_cast<const float4*>(bias)[lane]);
    float4 o;
    o.x = elu(acc[0] * inv + bb.x); o.y = elu(acc[1] * inv + bb.y);
    o.z = elu(acc[2] * inv + bb.z); o.w = elu(acc[3] * inv + bb.w);
    reinterpret_cast<float4*>(&g_out2[(size_t)d * D2])[lane] = o;
}

// ---------------- pooling (batch sorted -> segmented accumulation) ---------
#define NPB 128
__global__ void pool_k(const int* __restrict__ batch) {
    int c = threadIdx.x;
    int n0 = blockIdx.x * NPB;
    int n1 = min(NN, n0 + NPB);
    if (n0 >= NN) return;
    int curg = batch[n0];
    float acc = 0.f, cnt = 0.f;
    for (int n = n0; n < n1; n++) {
        int gg = batch[n];
        if (gg != curg) {
            atomicAdd(&g_pool[curg * D2 + c], acc);
            if (c == 0) atomicAdd(&g_cnt[curg], cnt);
            acc = 0.f; cnt = 0.f; curg = gg;
        }
        acc += g_out2[(size_t)n * D2 + c];
        cnt += 1.f;
    }
    atomicAdd(&g_pool[curg * D2 + c], acc);
    if (c == 0) atomicAdd(&g_cnt[curg], cnt);
}

__global__ void final_k(const float* __restrict__ lin_w, const float* __restrict__ lin_b,
                        float* __restrict__ out) {
    int t = threadIdx.x;
    if (t >= NG * NCLS) return;
    int gph = t / NCLS, k = t - gph * NCLS;
    float inv = 1.f / fmaxf(g_cnt[gph], 1.f);
    float acc = 0.f;
    for (int c = 0; c < D2; c++)
        acc = fmaf(g_pool[gph * D2 + c] * inv, __ldg(&lin_w[c * NCLS + k]), acc);
    out[t] = acc + lin_b[k];
}

// ---------------- driver -----------------------------------------------------
#define SMEM_G1 ((64 * (FIN + 8) + FIN * (D1 + 8)) * 2)
#define SMEM_G2 ((128 * (D1 + 8) + D1 * (D2 + 8)) * 2)

extern "C" void kernel_launch(void* const* d_in, const int* in_sizes, int n_in,
                              void* d_out, int out_size) {
    const float* x        = (const float*)d_in[0];
    const int*   ei       = (const int*)d_in[1];
    const int*   batch    = (const int*)d_in[2];
    const float* W1       = (const float*)d_in[3];
    const float* att_src1 = (const float*)d_in[4];
    const float* att_dst1 = (const float*)d_in[5];
    const float* b1       = (const float*)d_in[6];
    const float* W2       = (const float*)d_in[7];
    const float* att_src2 = (const float*)d_in[8];
    const float* att_dst2 = (const float*)d_in[9];
    const float* b2       = (const float*)d_in[10];
    const float* lin_w    = (const float*)d_in[11];
    const float* lin_b    = (const float*)d_in[12];
    float* out = (float*)d_out;

    static cudaStream_t s1 = 0;
    static cudaEvent_t evRoot = 0, evCsr = 0;
    static int inited = 0;
    if (!inited) {
        cudaStreamCreateWithFlags(&s1, cudaStreamNonBlocking);
        cudaEventCreateWithFlags(&evRoot, cudaEventDisableTiming);
        cudaEventCreateWithFlags(&evCsr, cudaEventDisableTiming);
        cudaFuncSetAttribute((const void*)gemm_tc_k<FIN, D1, 64, 4, 2, NH1, false>,
                             cudaFuncAttributeMaxDynamicSharedMemorySize, SMEM_G1);
        cudaFuncSetAttribute((const void*)gemm_tc_k<D1, D2, 128, 8, 1, 1, true>,
                             cudaFuncAttributeMaxDynamicSharedMemorySize, SMEM_G2);
        inited = 1;
    }

    __half* h1p;    cudaGetSymbolAddress((void**)&h1p, g_h1h);
    __half* out1hp; cudaGetSymbolAddress((void**)&out1hp, g_out1h);
    __half* h2p;    cudaGetSymbolAddress((void**)&h2p, g_h2h);
    __half* w1hp;   cudaGetSymbolAddress((void**)&w1hp, g_w1h);
    __half* w2hp;   cudaGetSymbolAddress((void**)&w2hp, g_w2h);
    float*  as1p;   cudaGetSymbolAddress((void**)&as1p, g_asrc1);
    float*  ad1p;   cudaGetSymbolAddress((void**)&ad1p, g_adst1);
    float*  as2p;   cudaGetSymbolAddress((void**)&as2p, g_asrc2);
    float*  ad2p;   cudaGetSymbolAddress((void**)&ad2p, g_adst2);

    // fork: CSR build on s1, GEMM path on stream 0
    cudaEventRecord(evRoot, 0);
    cudaStreamWaitEvent(s1, evRoot, 0);
    init_kernel<<<256, 256, 0, s1>>>();
    deg_k<<<(ET + 255) / 256, 256, 0, s1>>>(ei);
    scan_k<<<1, 1024, 0, s1>>>();
    scatter_k<<<(ET + 255) / 256, 256, 0, s1>>>(ei);
    cudaEventRecord(evCsr, s1);

    convw_k<<<128, 256>>>(W1, W2);
    gemm_tc_k<FIN, D1, 64, 4, 2, NH1, false><<<(NN + 63) / 64, 256, SMEM_G1>>>(
        x, w1hp, h1p, att_src1, att_dst1, as1p, ad1p);

    // join: agg needs CSR
    cudaStreamWaitEvent(0, evCsr, 0);
    agg1_k<<<(NN * 32 + 255) / 256, 256>>>(b1);

    gemm_tc_k<D1, D2, 128, 8, 1, 1, true><<<(NN + 127) / 128, 256, SMEM_G2>>>(
        out1hp, w2hp, h2p, att_src2, att_dst2, as2p, ad2p);
    agg2_k<<<(NN * 32 + 255) / 256, 256>>>(b2);

    pool_k<<<(NN + NPB - 1) / NPB, D2>>>(batch);
    final_k<<<1, 256>>>(lin_w, lin_b, out);
}

// round 14
// speedup vs baseline: 1.7511x; 1.0177x over previous
#include <cuda_runtime.h>
#include <cuda_fp16.h>

#define NN 50000
#define EE 800000
#define ET 850000        // EE + NN self loops
#define FIN 128
#define D1 256           // H1*C1 = 4*64
#define C1C 64
#define NH1 4
#define D2 128
#define NG 32
#define NCLS 5
#define NEG_SLOPE 0.2f

// ---------------- scratch (static device globals) ---------------------------
__device__ __half g_h1h[(size_t)NN * D1];    // layer1 features, fp16 (gather path)
__device__ __half g_out1h[(size_t)NN * D1];  // elu(agg)+bias of layer1, fp16 (GEMM2 input)
__device__ __half g_h2h[(size_t)NN * D2];    // layer2 features, fp16
__device__ float  g_out2[(size_t)NN * D2];
__device__ __half g_w1h[FIN * D1];
__device__ __half g_w2h[D1 * D2];
__device__ float  g_asrc1[NN * NH1], g_adst1[NN * NH1];
__device__ float  g_asrc2[NN], g_adst2[NN];
__device__ float  g_pool[NG * D2];
__device__ float  g_cnt[NG];
// CSR by destination (slot rowptr[d] pre-reserved for the self loop)
__device__ int g_deg[NN];
__device__ int g_rowptr[NN + 1];
__device__ int g_cursor[NN];
__device__ int g_col[ET];

__device__ __forceinline__ float lrelu(float a) { return (a > 0.f) ? a : NEG_SLOPE * a; }
__device__ __forceinline__ float elu(float v)   { return (v > 0.f) ? v : expm1f(v); }
__device__ __forceinline__ unsigned sptr(const void* p) {
    return (unsigned)__cvta_generic_to_shared(p);
}

// ---------------- init ------------------------------------------------------
__global__ void init_kernel() {
    int i0 = blockIdx.x * blockDim.x + threadIdx.x;
    int stride = gridDim.x * blockDim.x;
    for (int i = i0; i < NN; i += stride) g_deg[i] = 1;   // self loop pre-counted
    for (int i = i0; i < NG * D2; i += stride) g_pool[i] = 0.f;
    if (i0 < NG) g_cnt[i0] = 0.f;
}

// ---------------- W conversion to fp16 --------------------------------------
__global__ void convw_k(const float* __restrict__ W1, const float* __restrict__ W2) {
    int i = blockIdx.x * blockDim.x + threadIdx.x;   // 32768 of each
    if (i < FIN * D1) g_w1h[i] = __float2half(W1[i]);
    if (i < D1 * D2)  g_w2h[i] = __float2half(W2[i]);
}

// ---------------- CSR build (real edges only; int4-vectorized deg) ---------
__global__ void deg_k(const int* __restrict__ ei) {
    int t = blockIdx.x * blockDim.x + threadIdx.x;
    int base = t * 4;
    if (base >= EE) return;
    if (base + 4 <= EE) {
        int4 d4 = *reinterpret_cast<const int4*>(ei + EE + base);
        atomicAdd(&g_deg[d4.x], 1);
        atomicAdd(&g_deg[d4.y], 1);
        atomicAdd(&g_deg[d4.z], 1);
        atomicAdd(&g_deg[d4.w], 1);
    } else {
        for (int e = base; e < EE; e++) atomicAdd(&g_deg[ei[EE + e]], 1);
    }
}

__global__ void scan_k() {
    const int T = 1024;
    const int CH = (NN + T - 1) / T;
    __shared__ int part[T];
    int t = threadIdx.x;
    int base = t * CH;
    int s = 0;
    for (int i = 0; i < CH; i++) {
        int idx = base + i;
        if (idx < NN) s += g_deg[idx];
    }
    part[t] = s;
    __syncthreads();
    for (int off = 1; off < T; off <<= 1) {
        int v = (t >= off) ? part[t - off] : 0;
        __syncthreads();
        part[t] += v;
        __syncthreads();
    }
    int run = part[t] - s;
    for (int i = 0; i < CH; i++) {
        int idx = base + i;
        if (idx < NN) {
            g_rowptr[idx] = run;
            g_col[run] = idx;          // self loop in slot 0 of the row
            g_cursor[idx] = run + 1;
            run += g_deg[idx];
        }
    }
    if (t == 0) g_rowptr[NN] = ET;
}

__global__ void scatter_k(const int* __restrict__ ei) {
    int e = blockIdx.x * blockDim.x + threadIdx.x;
    if (e >= EE) return;
    int s = ei[e], d = ei[EE + e];
    int pos = atomicAdd(&g_cursor[d], 1);
    g_col[pos] = s;
}

// ---------------- tensor-core GEMM + fused attention scores ----------------
// A staged fully in smem; W staged in K-chunks of <=128 (halves smem for GEMM2).
template <int KDIM, int NDIM, int MBLK, int MW, int NW, int HEADS, bool A_FP16>
__global__ void __launch_bounds__(MW * NW * 32)
gemm_tc_k(const void* __restrict__ Ain, const __half* __restrict__ Wh,
          __half* __restrict__ H,
          const float* __restrict__ att_s, const float* __restrict__ att_d,
          float* __restrict__ asrc, float* __restrict__ adst) {
    constexpr int AST = KDIM + 8;                   // A smem row stride (halves)
    constexpr int WST = NDIM + 8;                   // W smem row stride (halves)
    constexpr int KCH = (KDIM > 128) ? 128 : KDIM;  // W k-chunk
    constexpr int NTHR = MW * NW * 32;
    constexpr int NWP = NDIM / NW;                  // cols per warp
    constexpr int NFRAG = NWP / 8;
    constexpr int SPAN = NDIM / HEADS;              // cols per head
    constexpr int JPH = SPAN / 8;                   // n-frags per head
    constexpr int HSLOTS = NWP / SPAN > 0 ? NWP / SPAN : 1;
    extern __shared__ __align__(16) __half smem[];
    __half* As = smem;                              // [MBLK][AST]
    __half* Ws = smem + MBLK * AST;                 // [KCH][WST]
    int tid = threadIdx.x;
    int row0 = blockIdx.x * MBLK;

    // stage A fully (convert fp32->fp16 if needed)
    for (int idx = tid; idx < MBLK * (KDIM / 8); idx += NTHR) {
        int m = idx / (KDIM / 8), kc = (idx % (KDIM / 8)) * 8;
        int r = row0 + m;
        uint4 pack = {0u, 0u, 0u, 0u};
        if (r < NN) {
            if (A_FP16) {
                pack = *reinterpret_cast<const uint4*>(
                    reinterpret_cast<const __half*>(Ain) + (size_t)r * KDIM + kc);
            } else {
                const float4* xp = reinterpret_cast<const float4*>(
                    reinterpret_cast<const float*>(Ain) + (size_t)r * KDIM + kc);
                float4 f0 = xp[0], f1 = xp[1];
                __half2 h0 = __floats2half2_rn(f0.x, f0.y);
                __half2 h1 = __floats2half2_rn(f0.z, f0.w);
                __half2 h2 = __floats2half2_rn(f1.x, f1.y);
                __half2 h3 = __floats2half2_rn(f1.z, f1.w);
                pack.x = *reinterpret_cast<unsigned*>(&h0);
                pack.y = *reinterpret_cast<unsigned*>(&h1);
                pack.z = *reinterpret_cast<unsigned*>(&h2);
                pack.w = *reinterpret_cast<unsigned*>(&h3);
            }
        }
        *reinterpret_cast<uint4*>(&As[m * AST + kc]) = pack;
    }

    int wid = tid >> 5, lane = tid & 31;
    int wm = wid % MW, wn = wid / MW;
    int mb = wm * 16, nb = wn * NWP;

    float acc[NFRAG][4];
#pragma unroll
    for (int j = 0; j < NFRAG; j++)
#pragma unroll
        for (int q = 0; q < 4; q++) acc[j][q] = 0.f;

    for (int kc = 0; kc < KDIM; kc += KCH) {
        if (kc) __syncthreads();                    // protect Ws reuse
        for (int idx = tid; idx < KCH * (NDIM / 8); idx += NTHR) {
            int k = idx / (NDIM / 8), nc = (idx % (NDIM / 8)) * 8;
            *reinterpret_cast<uint4*>(&Ws[k * WST + nc]) =
                *reinterpret_cast<const uint4*>(&Wh[(size_t)(kc + k) * NDIM + nc]);
        }
        __syncthreads();

        for (int k0 = 0; k0 < KCH; k0 += 16) {
            unsigned a0, a1, a2, a3;
            unsigned aaddr = sptr(&As[(mb + (lane & 15)) * AST + kc + k0 + (lane >> 4) * 8]);
            asm volatile("ldmatrix.sync.aligned.m8n8.x4.shared.b16 {%0,%1,%2,%3}, [%4];"
                         : "=r"(a0), "=r"(a1), "=r"(a2), "=r"(a3) : "r"(aaddr));
#pragma unroll
            for (int j = 0; j < NFRAG; j++) {
                unsigned b0, b1;
                unsigned baddr = sptr(&Ws[(k0 + (lane & 15)) * WST + nb + j * 8]);
                asm volatile("ldmatrix.sync.aligned.m8n8.x2.trans.shared.b16 {%0,%1}, [%2];"
                             : "=r"(b0), "=r"(b1) : "r"(baddr));
                asm volatile("mma.sync.aligned.m16n8k16.row.col.f32.f16.f16.f32 "
                             "{%0,%1,%2,%3}, {%4,%5,%6,%7}, {%8,%9}, {%0,%1,%2,%3};"
                             : "+f"(acc[j][0]), "+f"(acc[j][1]), "+f"(acc[j][2]), "+f"(acc[j][3])
                             : "r"(a0), "r"(a1), "r"(a2), "r"(a3), "r"(b0), "r"(b1));
            }
        }
    }

    // epilogue: store H (fp16) + fused score dots
    float sS[2][HSLOTS], sD[2][HSLOTS];
#pragma unroll
    for (int r = 0; r < 2; r++)
#pragma unroll
        for (int hs = 0; hs < HSLOTS; hs++) { sS[r][hs] = 0.f; sD[r][hs] = 0.f; }
    int rg0 = row0 + mb + (lane >> 2);              // rows rg0, rg0+8
#pragma unroll
    for (int j = 0; j < NFRAG; j++) {
        int c0 = nb + j * 8 + (lane & 3) * 2;
        float as0 = __ldg(&att_s[c0]), as1 = __ldg(&att_s[c0 + 1]);
        float ad0 = __ldg(&att_d[c0]), ad1 = __ldg(&att_d[c0 + 1]);
        int slot = j / JPH;
        sS[0][slot] += acc[j][0] * as0 + acc[j][1] * as1;
        sS[1][slot] += acc[j][2] * as0 + acc[j][3] * as1;
        sD[0][slot] += acc[j][0] * ad0 + acc[j][1] * ad1;
        sD[1][slot] += acc[j][2] * ad0 + acc[j][3] * ad1;
        if (rg0 < NN) {
            __half2 hv = __floats2half2_rn(acc[j][0], acc[j][1]);
            *reinterpret_cast<__half2*>(&H[(size_t)rg0 * NDIM + c0]) = hv;
        }
        if (rg0 + 8 < NN) {
            __half2 hv = __floats2half2_rn(acc[j][2], acc[j][3]);
            *reinterpret_cast<__half2*>(&H[(size_t)(rg0 + 8) * NDIM + c0]) = hv;
        }
    }
#pragma unroll
    for (int r = 0; r < 2; r++)
#pragma unroll
        for (int hs = 0; hs < HSLOTS; hs++) {
            sS[r][hs] += __shfl_xor_sync(0xffffffffu, sS[r][hs], 1);
            sS[r][hs] += __shfl_xor_sync(0xffffffffu, sS[r][hs], 2);
            sD[r][hs] += __shfl_xor_sync(0xffffffffu, sD[r][hs], 1);
            sD[r][hs] += __shfl_xor_sync(0xffffffffu, sD[r][hs], 2);
        }
    if ((lane & 3) == 0) {
        int hbase = nb / SPAN;
#pragma unroll
        for (int hs = 0; hs < HSLOTS; hs++) {
            int h = hbase + hs;
            if (rg0 < NN) {
                asrc[rg0 * HEADS + h] = sS[0][hs];
                adst[rg0 * HEADS + h] = sD[0][hs];
            }
            if (rg0 + 8 < NN) {
                asrc[(rg0 + 8) * HEADS + h] = sS[1][hs];
                adst[(rg0 + 8) * HEADS + h] = sD[1][hs];
            }
        }
    }
}

// ---------------- fused softmax + aggregation (warp per dst, fp16 gather) --
// layer1: 4 heads, 256 channels. lane owns channels [8*lane, 8*lane+8) in head lane>>3.
__global__ void agg1_k(const float* __restrict__ bias) {
    int g = blockIdx.x * blockDim.x + threadIdx.x;
    int d = g >> 5, lane = g & 31;
    if (d >= NN) return;
    int b = g_rowptr[d];
    int deg = g_rowptr[d + 1] - b;
    float ad0 = g_adst1[d * NH1 + 0], ad1 = g_adst1[d * NH1 + 1];
    float ad2 = g_adst1[d * NH1 + 2], ad3 = g_adst1[d * NH1 + 3];

    float mx0 = -1e30f, mx1 = -1e30f, mx2 = -1e30f, mx3 = -1e30f;
    for (int i = lane; i < deg; i += 32) {
        int s = g_col[b + i];
        float4 a = *reinterpret_cast<const float4*>(&g_asrc1[s * NH1]);
        mx0 = fmaxf(mx0, lrelu(a.x + ad0));
        mx1 = fmaxf(mx1, lrelu(a.y + ad1));
        mx2 = fmaxf(mx2, lrelu(a.z + ad2));
        mx3 = fmaxf(mx3, lrelu(a.w + ad3));
    }
#pragma unroll
    for (int o = 16; o; o >>= 1) {
        mx0 = fmaxf(mx0, __shfl_xor_sync(0xffffffffu, mx0, o));
        mx1 = fmaxf(mx1, __shfl_xor_sync(0xffffffffu, mx1, o));
        mx2 = fmaxf(mx2, __shfl_xor_sync(0xffffffffu, mx2, o));
        mx3 = fmaxf(mx3, __shfl_xor_sync(0xffffffffu, mx3, o));
    }

    int h = lane >> 3;
    float adS = (h == 0) ? ad0 : (h == 1) ? ad1 : (h == 2) ? ad2 : ad3;
    float mxS = (h == 0) ? mx0 : (h == 1) ? mx1 : (h == 2) ? mx2 : mx3;
    float den = 0.f;
    float acc[8];
#pragma unroll
    for (int q = 0; q < 8; q++) acc[q] = 0.f;

    // depth-3 software pipeline
    int sA = g_col[b];
    int sB = g_col[b + min(1, deg - 1)];
    float aA = g_asrc1[sA * NH1 + h];
    float aB = g_asrc1[sB * NH1 + h];
    uint4 vA = *reinterpret_cast<const uint4*>(&g_h1h[(size_t)sA * D1 + lane * 8]);
    uint4 vB = *reinterpret_cast<const uint4*>(&g_h1h[(size_t)sB * D1 + lane * 8]);
    for (int i = 0; i < deg; i++) {
        int j = min(i + 2, deg - 1);
        int sC = g_col[b + j];
        float aC = g_asrc1[sC * NH1 + h];
        uint4 vC = *reinterpret_cast<const uint4*>(&g_h1h[(size_t)sC * D1 + lane * 8]);
        float e = __expf(lrelu(aA + adS) - mxS);
        den += e;
        const __half2* hp = reinterpret_cast<const __half2*>(&vA);
#pragma unroll
        for (int q = 0; q < 4; q++) {
            float2 f = __half22float2(hp[q]);
            acc[2 * q]     = fmaf(f.x, e, acc[2 * q]);
            acc[2 * q + 1] = fmaf(f.y, e, acc[2 * q + 1]);
        }
        aA = aB; vA = vB; aB = aC; vB = vC;
    }
    float inv = 1.f / (den + 1e-16f);
    float4 b0 = __ldg(&reinterpret_cast<const float4*>(bias)[2 * lane]);
    float4 b1 = __ldg(&reinterpret_cast<const float4*>(bias)[2 * lane + 1]);
    float o0 = elu(acc[0] * inv + b0.x), o1 = elu(acc[1] * inv + b0.y);
    float o2 = elu(acc[2] * inv + b0.z), o3 = elu(acc[3] * inv + b0.w);
    float o4 = elu(acc[4] * inv + b1.x), o5 = elu(acc[5] * inv + b1.y);
    float o6 = elu(acc[6] * inv + b1.z), o7 = elu(acc[7] * inv + b1.w);
    __half2 p0 = __floats2half2_rn(o0, o1), p1 = __floats2half2_rn(o2, o3);
    __half2 p2 = __floats2half2_rn(o4, o5), p3 = __floats2half2_rn(o6, o7);
    uint4 pack;
    pack.x = *reinterpret_cast<unsigned*>(&p0);
    pack.y = *reinterpret_cast<unsigned*>(&p1);
    pack.z = *reinterpret_cast<unsigned*>(&p2);
    pack.w = *reinterpret_cast<unsigned*>(&p3);
    *reinterpret_cast<uint4*>(&g_out1h[(size_t)d * D1 + lane * 8]) = pack;
}

// layer2: 1 head, 128 channels; lane owns 4 channels
__global__ void agg2_k(const float* __restrict__ bias) {
    int g = blockIdx.x * blockDim.x + threadIdx.x;
    int d = g >> 5, lane = g & 31;
    if (d >= NN) return;
    int b = g_rowptr[d];
    int deg = g_rowptr[d + 1] - b;
    float ad = g_adst2[d];
    float mx = -1e30f;
    for (int i = lane; i < deg; i += 32) {
        int s = g_col[b + i];
        mx = fmaxf(mx, lrelu(g_asrc2[s] + ad));
    }
#pragma unroll
    for (int o = 16; o; o >>= 1) mx = fmaxf(mx, __shfl_xor_sync(0xffffffffu, mx, o));

    float den = 0.f;
    float acc[4];
#pragma unroll
    for (int q = 0; q < 4; q++) acc[q] = 0.f;

    int sA = g_col[b];
    int sB = g_col[b + min(1, deg - 1)];
    float aA = g_asrc2[sA];
    float aB = g_asrc2[sB];
    uint2 vA = *reinterpret_cast<const uint2*>(&g_h2h[(size_t)sA * D2 + lane * 4]);
    uint2 vB = *reinterpret_cast<const uint2*>(&g_h2h[(size_t)sB * D2 + lane * 4]);
    for (int i = 0; i < deg; i++) {
        int j = min(i + 2, deg - 1);
        int sC = g_col[b + j];
        float aC = g_asrc2[sC];
        uint2 vC = *reinterpret_cast<const uint2*>(&g_h2h[(size_t)sC * D2 + lane * 4]);
        float e = __expf(lrelu(aA + ad) - mx);
        den += e;
        const __half2* hp = reinterpret_cast<const __half2*>(&vA);
#pragma unroll
        for (int q = 0; q < 2; q++) {
            float2 f = __half22float2(hp[q]);
            acc[2 * q]     = fmaf(f.x, e, acc[2 * q]);
            acc[2 * q + 1] = fmaf(f.y, e, acc[2 * q + 1]);
        }
        aA = aB; vA = vB; aB = aC; vB = vC;
    }
    float inv = 1.f / (den + 1e-16f);
    float4 bb = __ldg(&reinterpret_cast<const float4*>(bias)[lane]);
    float4 o;
    o.x = elu(acc[0] * inv + bb.x); o.y = elu(acc[1] * inv + bb.y);
    o.z = elu(acc[2] * inv + bb.z); o.w = elu(acc[3] * inv + bb.w);
    reinterpret_cast<float4*>(&g_out2[(size_t)d * D2])[lane] = o;
}

// ---------------- pooling (batch sorted -> segmented accumulation) ---------
#define NPB 128
__global__ void pool_k(const int* __restrict__ batch) {
    int c = threadIdx.x;
    int n0 = blockIdx.x * NPB;
    int n1 = min(NN, n0 + NPB);
    if (n0 >= NN) return;
    int curg = batch[n0];
    float acc = 0.f, cnt = 0.f;
    for (int n = n0; n < n1; n++) {
        int gg = batch[n];
        if (gg != curg) {
            atomicAdd(&g_pool[curg * D2 + c], acc);
            if (c == 0) atomicAdd(&g_cnt[curg], cnt);
            acc = 0.f; cnt = 0.f; curg = gg;
        }
        acc += g_out2[(size_t)n * D2 + c];
        cnt += 1.f;
    }
    atomicAdd(&g_pool[curg * D2 + c], acc);
    if (c == 0) atomicAdd(&g_cnt[curg], cnt);
}

__global__ void final_k(const float* __restrict__ lin_w, const float* __restrict__ lin_b,
                        float* __restrict__ out) {
    int t = threadIdx.x;
    if (t >= NG * NCLS) return;
    int gph = t / NCLS, k = t - gph * NCLS;
    float inv = 1.f / fmaxf(g_cnt[gph], 1.f);
    float acc = 0.f;
    for (int c = 0; c < D2; c++)
        acc = fmaf(g_pool[gph * D2 + c] * inv, __ldg(&lin_w[c * NCLS + k]), acc);
    out[t] = acc + lin_b[k];
}

// ---------------- driver -----------------------------------------------------
#define SMEM_G1 ((64 * (FIN + 8) + FIN * (D1 + 8)) * 2)
#define SMEM_G2 ((128 * (D1 + 8) + 128 * (D2 + 8)) * 2)

extern "C" void kernel_launch(void* const* d_in, const int* in_sizes, int n_in,
                              void* d_out, int out_size) {
    const float* x        = (const float*)d_in[0];
    const int*   ei       = (const int*)d_in[1];
    const int*   batch    = (const int*)d_in[2];
    const float* W1       = (const float*)d_in[3];
    const float* att_src1 = (const float*)d_in[4];
    const float* att_dst1 = (const float*)d_in[5];
    const float* b1       = (const float*)d_in[6];
    const float* W2       = (const float*)d_in[7];
    const float* att_src2 = (const float*)d_in[8];
    const float* att_dst2 = (const float*)d_in[9];
    const float* b2       = (const float*)d_in[10];
    const float* lin_w    = (const float*)d_in[11];
    const float* lin_b    = (const float*)d_in[12];
    float* out = (float*)d_out;

    static cudaStream_t s1 = 0;
    static cudaEvent_t evRoot = 0, evCsr = 0;
    static int inited = 0;
    if (!inited) {
        cudaStreamCreateWithFlags(&s1, cudaStreamNonBlocking);
        cudaEventCreateWithFlags(&evRoot, cudaEventDisableTiming);
        cudaEventCreateWithFlags(&evCsr, cudaEventDisableTiming);
        cudaFuncSetAttribute((const void*)gemm_tc_k<FIN, D1, 64, 4, 2, NH1, false>,
                             cudaFuncAttributeMaxDynamicSharedMemorySize, SMEM_G1);
        cudaFuncSetAttribute((const void*)gemm_tc_k<D1, D2, 128, 8, 1, 1, true>,
                             cudaFuncAttributeMaxDynamicSharedMemorySize, SMEM_G2);
        inited = 1;
    }

    __half* h1p;    cudaGetSymbolAddress((void**)&h1p, g_h1h);
    __half* out1hp; cudaGetSymbolAddress((void**)&out1hp, g_out1h);
    __half* h2p;    cudaGetSymbolAddress((void**)&h2p, g_h2h);
    __half* w1hp;   cudaGetSymbolAddress((void**)&w1hp, g_w1h);
    __half* w2hp;   cudaGetSymbolAddress((void**)&w2hp, g_w2h);
    float*  as1p;   cudaGetSymbolAddress((void**)&as1p, g_asrc1);
    float*  ad1p;   cudaGetSymbolAddress((void**)&ad1p, g_adst1);
    float*  as2p;   cudaGetSymbolAddress((void**)&as2p, g_asrc2);
    float*  ad2p;   cudaGetSymbolAddress((void**)&ad2p, g_adst2);

    // fork: CSR build on s1, GEMM path on stream 0
    cudaEventRecord(evRoot, 0);
    cudaStreamWaitEvent(s1, evRoot, 0);
    init_kernel<<<256, 256, 0, s1>>>();
    deg_k<<<(EE / 4 + 255) / 256, 256, 0, s1>>>(ei);
    scan_k<<<1, 1024, 0, s1>>>();
    scatter_k<<<(EE + 255) / 256, 256, 0, s1>>>(ei);
    cudaEventRecord(evCsr, s1);

    convw_k<<<128, 256>>>(W1, W2);
    gemm_tc_k<FIN, D1, 64, 4, 2, NH1, false><<<(NN + 63) / 64, 256, SMEM_G1>>>(
        x, w1hp, h1p, att_src1, att_dst1, as1p, ad1p);

    // join: agg needs CSR
    cudaStreamWaitEvent(0, evCsr, 0);
    agg1_k<<<(NN * 32 + 255) / 256, 256>>>(b1);

    gemm_tc_k<D1, D2, 128, 8, 1, 1, true><<<(NN + 127) / 128, 256, SMEM_G2>>>(
        out1hp, w2hp, h2p, att_src2, att_dst2, as2p, ad2p);
    agg2_k<<<(NN * 32 + 255) / 256, 256>>>(b2);

    pool_k<<<(NN + NPB - 1) / NPB, D2>>>(batch);
    final_k<<<1, 256>>>(lin_w, lin_b, out);
}

// round 15
// speedup vs baseline: 2.5677x; 1.4664x over previous
#include <cuda_runtime.h>
#include <cuda_fp16.h>

#define NN 50000
#define EE 800000
#define ET 850000        // EE + NN self loops
#define FIN 128
#define D1 256           // H1*C1 = 4*64
#define C1C 64
#define NH1 4
#define D2 128
#define NG 32
#define NCLS 5
#define NEG_SLOPE 0.2f

// chunked scan
#define NCH 2048
#define CHW 25           // NCH*CHW = 51200 >= NN

// ---------------- scratch (static device globals; zero-init at module load) -
__device__ __half g_h1h[(size_t)NN * D1];
__device__ __half g_out1h[(size_t)NN * D1];
__device__ __half g_h2h[(size_t)NN * D2];
__device__ float  g_out2[(size_t)NN * D2];
__device__ __half g_w1h[FIN * D1];
__device__ __half g_w2h[D1 * D2];
__device__ float  g_asrc1[NN * NH1], g_adst1[NN * NH1];
__device__ float  g_asrc2[NN], g_adst2[NN];
__device__ float  g_pool[NG * D2];
__device__ float  g_cnt[NG];
// CSR by destination (slot rowptr[d] holds the self loop)
__device__ int g_deg[NN];            // real-edge in-degree; re-zeroed at graph end
__device__ int g_rowptr[NN + 1];
__device__ int g_cursor[NN];
__device__ int g_col[ET];
__device__ int g_csum[NCH], g_cpre[NCH];

__device__ __forceinline__ float lrelu(float a) { return (a > 0.f) ? a : NEG_SLOPE * a; }
__device__ __forceinline__ float elu(float v)   { return (v > 0.f) ? v : expm1f(v); }
__device__ __forceinline__ unsigned sptr(const void* p) {
    return (unsigned)__cvta_generic_to_shared(p);
}

// ---------------- W conversion to fp16 --------------------------------------
__global__ void convw_k(const float* __restrict__ W1, const float* __restrict__ W2) {
    int i = blockIdx.x * blockDim.x + threadIdx.x;
    if (i < FIN * D1) g_w1h[i] = __float2half(W1[i]);
    if (i < D1 * D2)  g_w2h[i] = __float2half(W2[i]);
}

// ---------------- CSR build --------------------------------------------------
// deg over real edges only; 8 edges per thread for MLP
__global__ void deg_k(const int* __restrict__ ei) {
    int t = blockIdx.x * blockDim.x + threadIdx.x;
    int base = t * 8;
    if (base >= EE) return;
    int4 a = *reinterpret_cast<const int4*>(ei + EE + base);
    int4 b = *reinterpret_cast<const int4*>(ei + EE + base + 4);
    atomicAdd(&g_deg[a.x], 1); atomicAdd(&g_deg[a.y], 1);
    atomicAdd(&g_deg[a.z], 1); atomicAdd(&g_deg[a.w], 1);
    atomicAdd(&g_deg[b.x], 1); atomicAdd(&g_deg[b.y], 1);
    atomicAdd(&g_deg[b.z], 1); atomicAdd(&g_deg[b.w], 1);
}

// chunk partial sums (+ zero pool/cnt off the critical path)
__global__ void csum_k() {
    int t = blockIdx.x * blockDim.x + threadIdx.x;   // 0..NCH-1
    if (blockIdx.x == 0) {
        for (int i = threadIdx.x; i < NG * D2; i += blockDim.x) g_pool[i] = 0.f;
        if (threadIdx.x < NG) g_cnt[threadIdx.x] = 0.f;
    }
    if (t >= NCH) return;
    int base = t * CHW;
    int s = 0;
#pragma unroll
    for (int i = 0; i < CHW; i++) {
        int idx = base + i;
        if (idx < NN) s += g_deg[idx];
    }
    g_csum[t] = s;
}

// single-block scan over NCH=2048 chunk sums (2 per thread)
__global__ void scanc_k() {
    __shared__ int part[1024];
    int t = threadIdx.x;
    int c0 = g_csum[2 * t], c1 = g_csum[2 * t + 1];
    int s = c0 + c1;
    part[t] = s;
    __syncthreads();
    for (int off = 1; off < 1024; off <<= 1) {
        int v = (t >= off) ? part[t - off] : 0;
        __syncthreads();
        part[t] += v;
        __syncthreads();
    }
    int run = part[t] - s;                 // exclusive prefix
    g_cpre[2 * t] = run;
    g_cpre[2 * t + 1] = run + c0;
    if (t == 0) g_rowptr[NN] = ET;
}

// fill rowptr/cursor/self-loops; rowptr[idx] = edge_prefix(idx) + idx
__global__ void fill_k() {
    int t = blockIdx.x * blockDim.x + threadIdx.x;   // 0..NCH-1
    if (t >= NCH) return;
    int base = t * CHW;
    int run = g_cpre[t];
#pragma unroll
    for (int i = 0; i < CHW; i++) {
        int idx = base + i;
        if (idx < NN) {
            int rp = run + idx;
            g_rowptr[idx] = rp;
            g_col[rp] = idx;               // self loop in slot 0
            g_cursor[idx] = rp + 1;
            run += g_deg[idx];
        }
    }
}

// scatter real edges; 2 per thread for atomic MLP
__global__ void scatter_k(const int* __restrict__ ei) {
    int t = blockIdx.x * blockDim.x + threadIdx.x;
    int e = t * 2;
    if (e >= EE) return;
    int2 s2 = *reinterpret_cast<const int2*>(ei + e);
    int2 d2 = *reinterpret_cast<const int2*>(ei + EE + e);
    int p0 = atomicAdd(&g_cursor[d2.x], 1);
    int p1 = atomicAdd(&g_cursor[d2.y], 1);
    g_col[p0] = s2.x;
    g_col[p1] = s2.y;
}

// zero deg for the next graph replay (off critical path)
__global__ void zdeg_k() {
    int i = blockIdx.x * blockDim.x + threadIdx.x;
    if (i < NN) g_deg[i] = 0;
}

// ---------------- tensor-core GEMM + fused attention scores ----------------
template <int KDIM, int NDIM, int MBLK, int MW, int NW, int HEADS, bool A_FP16>
__global__ void __launch_bounds__(MW * NW * 32)
gemm_tc_k(const void* __restrict__ Ain, const __half* __restrict__ Wh,
          __half* __restrict__ H,
          const float* __restrict__ att_s, const float* __restrict__ att_d,
          float* __restrict__ asrc, float* __restrict__ adst) {
    constexpr int AST = KDIM + 8;
    constexpr int WST = NDIM + 8;
    constexpr int KCH = (KDIM > 128) ? 128 : KDIM;
    constexpr int NTHR = MW * NW * 32;
    constexpr int NWP = NDIM / NW;
    constexpr int NFRAG = NWP / 8;
    constexpr int SPAN = NDIM / HEADS;
    constexpr int JPH = SPAN / 8;
    constexpr int HSLOTS = NWP / SPAN > 0 ? NWP / SPAN : 1;
    extern __shared__ __align__(16) __half smem[];
    __half* As = smem;
    __half* Ws = smem + MBLK * AST;
    int tid = threadIdx.x;
    int row0 = blockIdx.x * MBLK;

    for (int idx = tid; idx < MBLK * (KDIM / 8); idx += NTHR) {
        int m = idx / (KDIM / 8), kc = (idx % (KDIM / 8)) * 8;
        int r = row0 + m;
        uint4 pack = {0u, 0u, 0u, 0u};
        if (r < NN) {
            if (A_FP16) {
                pack = *reinterpret_cast<const uint4*>(
                    reinterpret_cast<const __half*>(Ain) + (size_t)r * KDIM + kc);
            } else {
                const float4* xp = reinterpret_cast<const float4*>(
                    reinterpret_cast<const float*>(Ain) + (size_t)r * KDIM + kc);
                float4 f0 = xp[0], f1 = xp[1];
                __half2 h0 = __floats2half2_rn(f0.x, f0.y);
                __half2 h1 = __floats2half2_rn(f0.z, f0.w);
                __half2 h2 = __floats2half2_rn(f1.x, f1.y);
                __half2 h3 = __floats2half2_rn(f1.z, f1.w);
                pack.x = *reinterpret_cast<unsigned*>(&h0);
                pack.y = *reinterpret_cast<unsigned*>(&h1);
                pack.z = *reinterpret_cast<unsigned*>(&h2);
                pack.w = *reinterpret_cast<unsigned*>(&h3);
            }
        }
        *reinterpret_cast<uint4*>(&As[m * AST + kc]) = pack;
    }

    int wid = tid >> 5, lane = tid & 31;
    int wm = wid % MW, wn = wid / MW;
    int mb = wm * 16, nb = wn * NWP;

    float acc[NFRAG][4];
#pragma unroll
    for (int j = 0; j < NFRAG; j++)
#pragma unroll
        for (int q = 0; q < 4; q++) acc[j][q] = 0.f;

    for (int kc = 0; kc < KDIM; kc += KCH) {
        if (kc) __syncthreads();
        for (int idx = tid; idx < KCH * (NDIM / 8); idx += NTHR) {
            int k = idx / (NDIM / 8), nc = (idx % (NDIM / 8)) * 8;
            *reinterpret_cast<uint4*>(&Ws[k * WST + nc]) =
                *reinterpret_cast<const uint4*>(&Wh[(size_t)(kc + k) * NDIM + nc]);
        }
        __syncthreads();

        for (int k0 = 0; k0 < KCH; k0 += 16) {
            unsigned a0, a1, a2, a3;
            unsigned aaddr = sptr(&As[(mb + (lane & 15)) * AST + kc + k0 + (lane >> 4) * 8]);
            asm volatile("ldmatrix.sync.aligned.m8n8.x4.shared.b16 {%0,%1,%2,%3}, [%4];"
                         : "=r"(a0), "=r"(a1), "=r"(a2), "=r"(a3) : "r"(aaddr));
#pragma unroll
            for (int j = 0; j < NFRAG; j++) {
                unsigned b0, b1;
                unsigned baddr = sptr(&Ws[(k0 + (lane & 15)) * WST + nb + j * 8]);
                asm volatile("ldmatrix.sync.aligned.m8n8.x2.trans.shared.b16 {%0,%1}, [%2];"
                             : "=r"(b0), "=r"(b1) : "r"(baddr));
                asm volatile("mma.sync.aligned.m16n8k16.row.col.f32.f16.f16.f32 "
                             "{%0,%1,%2,%3}, {%4,%5,%6,%7}, {%8,%9}, {%0,%1,%2,%3};"
                             : "+f"(acc[j][0]), "+f"(acc[j][1]), "+f"(acc[j][2]), "+f"(acc[j][3])
                             : "r"(a0), "r"(a1), "r"(a2), "r"(a3), "r"(b0), "r"(b1));
            }
        }
    }

    float sS[2][HSLOTS], sD[2][HSLOTS];
#pragma unroll
    for (int r = 0; r < 2; r++)
#pragma unroll
        for (int hs = 0; hs < HSLOTS; hs++) { sS[r][hs] = 0.f; sD[r][hs] = 0.f; }
    int rg0 = row0 + mb + (lane >> 2);
#pragma unroll
    for (int j = 0; j < NFRAG; j++) {
        int c0 = nb + j * 8 + (lane & 3) * 2;
        float as0 = __ldg(&att_s[c0]), as1 = __ldg(&att_s[c0 + 1]);
        float ad0 = __ldg(&att_d[c0]), ad1 = __ldg(&att_d[c0 + 1]);
        int slot = j / JPH;
        sS[0][slot] += acc[j][0] * as0 + acc[j][1] * as1;
        sS[1][slot] += acc[j][2] * as0 + acc[j][3] * as1;
        sD[0][slot] += acc[j][0] * ad0 + acc[j][1] * ad1;
        sD[1][slot] += acc[j][2] * ad0 + acc[j][3] * ad1;
        if (rg0 < NN) {
            __half2 hv = __floats2half2_rn(acc[j][0], acc[j][1]);
            *reinterpret_cast<__half2*>(&H[(size_t)rg0 * NDIM + c0]) = hv;
        }
        if (rg0 + 8 < NN) {
            __half2 hv = __floats2half2_rn(acc[j][2], acc[j][3]);
            *reinterpret_cast<__half2*>(&H[(size_t)(rg0 + 8) * NDIM + c0]) = hv;
        }
    }
#pragma unroll
    for (int r = 0; r < 2; r++)
#pragma unroll
        for (int hs = 0; hs < HSLOTS; hs++) {
            sS[r][hs] += __shfl_xor_sync(0xffffffffu, sS[r][hs], 1);
            sS[r][hs] += __shfl_xor_sync(0xffffffffu, sS[r][hs], 2);
            sD[r][hs] += __shfl_xor_sync(0xffffffffu, sD[r][hs], 1);
            sD[r][hs] += __shfl_xor_sync(0xffffffffu, sD[r][hs], 2);
        }
    if ((lane & 3) == 0) {
        int hbase = nb / SPAN;
#pragma unroll
        for (int hs = 0; hs < HSLOTS; hs++) {
            int h = hbase + hs;
            if (rg0 < NN) {
                asrc[rg0 * HEADS + h] = sS[0][hs];
                adst[rg0 * HEADS + h] = sD[0][hs];
            }
            if (rg0 + 8 < NN) {
                asrc[(rg0 + 8) * HEADS + h] = sS[1][hs];
                adst[(rg0 + 8) * HEADS + h] = sD[1][hs];
            }
        }
    }
}

// ---------------- fused softmax + aggregation (warp per dst, fp16 gather) --
__global__ void agg1_k(const float* __restrict__ bias) {
    int g = blockIdx.x * blockDim.x + threadIdx.x;
    int d = g >> 5, lane = g & 31;
    if (d >= NN) return;
    int b = g_rowptr[d];
    int deg = g_rowptr[d + 1] - b;
    float ad0 = g_adst1[d * NH1 + 0], ad1 = g_adst1[d * NH1 + 1];
    float ad2 = g_adst1[d * NH1 + 2], ad3 = g_adst1[d * NH1 + 3];

    float mx0 = -1e30f, mx1 = -1e30f, mx2 = -1e30f, mx3 = -1e30f;
    for (int i = lane; i < deg; i += 32) {
        int s = g_col[b + i];
        float4 a = *reinterpret_cast<const float4*>(&g_asrc1[s * NH1]);
        mx0 = fmaxf(mx0, lrelu(a.x + ad0));
        mx1 = fmaxf(mx1, lrelu(a.y + ad1));
        mx2 = fmaxf(mx2, lrelu(a.z + ad2));
        mx3 = fmaxf(mx3, lrelu(a.w + ad3));
    }
#pragma unroll
    for (int o = 16; o; o >>= 1) {
        mx0 = fmaxf(mx0, __shfl_xor_sync(0xffffffffu, mx0, o));
        mx1 = fmaxf(mx1, __shfl_xor_sync(0xffffffffu, mx1, o));
        mx2 = fmaxf(mx2, __shfl_xor_sync(0xffffffffu, mx2, o));
        mx3 = fmaxf(mx3, __shfl_xor_sync(0xffffffffu, mx3, o));
    }

    int h = lane >> 3;
    float adS = (h == 0) ? ad0 : (h == 1) ? ad1 : (h == 2) ? ad2 : ad3;
    float mxS = (h == 0) ? mx0 : (h == 1) ? mx1 : (h == 2) ? mx2 : mx3;
    float den = 0.f;
    float acc[8];
#pragma unroll
    for (int q = 0; q < 8; q++) acc[q] = 0.f;

    int sA = g_col[b];
    int sB = g_col[b + min(1, deg - 1)];
    float aA = g_asrc1[sA * NH1 + h];
    float aB = g_asrc1[sB * NH1 + h];
    uint4 vA = __ldg(reinterpret_cast<const uint4*>(&g_h1h[(size_t)sA * D1 + lane * 8]));
    uint4 vB = __ldg(reinterpret_cast<const uint4*>(&g_h1h[(size_t)sB * D1 + lane * 8]));
    for (int i = 0; i < deg; i++) {
        int j = min(i + 2, deg - 1);
        int sC = g_col[b + j];
        float aC = g_asrc1[sC * NH1 + h];
        uint4 vC = __ldg(reinterpret_cast<const uint4*>(&g_h1h[(size_t)sC * D1 + lane * 8]));
        float e = __expf(lrelu(aA + adS) - mxS);
        den += e;
        const __half2* hp = reinterpret_cast<const __half2*>(&vA);
#pragma unroll
        for (int q = 0; q < 4; q++) {
            float2 f = __half22float2(hp[q]);
            acc[2 * q]     = fmaf(f.x, e, acc[2 * q]);
            acc[2 * q + 1] = fmaf(f.y, e, acc[2 * q + 1]);
        }
        aA = aB; vA = vB; aB = aC; vB = vC;
    }
    float inv = 1.f / (den + 1e-16f);
    float4 b0 = __ldg(&reinterpret_cast<const float4*>(bias)[2 * lane]);
    float4 b1 = __ldg(&reinterpret_cast<const float4*>(bias)[2 * lane + 1]);
    float o0 = elu(acc[0] * inv + b0.x), o1 = elu(acc[1] * inv + b0.y);
    float o2 = elu(acc[2] * inv + b0.z), o3 = elu(acc[3] * inv + b0.w);
    float o4 = elu(acc[4] * inv + b1.x), o5 = elu(acc[5] * inv + b1.y);
    float o6 = elu(acc[6] * inv + b1.z), o7 = elu(acc[7] * inv + b1.w);
    __half2 p0 = __floats2half2_rn(o0, o1), p1 = __floats2half2_rn(o2, o3);
    __half2 p2 = __floats2half2_rn(o4, o5), p3 = __floats2half2_rn(o6, o7);
    uint4 pack;
    pack.x = *reinterpret_cast<unsigned*>(&p0);
    pack.y = *reinterpret_cast<unsigned*>(&p1);
    pack.z = *reinterpret_cast<unsigned*>(&p2);
    pack.w = *reinterpret_cast<unsigned*>(&p3);
    *reinterpret_cast<uint4*>(&g_out1h[(size_t)d * D1 + lane * 8]) = pack;
}

__global__ void agg2_k(const float* __restrict__ bias) {
    int g = blockIdx.x * blockDim.x + threadIdx.x;
    int d = g >> 5, lane = g & 31;
    if (d >= NN) return;
    int b = g_rowptr[d];
    int deg = g_rowptr[d + 1] - b;
    float ad = g_adst2[d];
    float mx = -1e30f;
    for (int i = lane; i < deg; i += 32) {
        int s = g_col[b + i];
        mx = fmaxf(mx, lrelu(g_asrc2[s] + ad));
    }
#pragma unroll
    for (int o = 16; o; o >>= 1) mx = fmaxf(mx, __shfl_xor_sync(0xffffffffu, mx, o));

    float den = 0.f;
    float acc[4];
#pragma unroll
    for (int q = 0; q < 4; q++) acc[q] = 0.f;

    int sA = g_col[b];
    int sB = g_col[b + min(1, deg - 1)];
    float aA = g_asrc2[sA];
    float aB = g_asrc2[sB];
    uint2 vA = __ldg(reinterpret_cast<const uint2*>(&g_h2h[(size_t)sA * D2 + lane * 4]));
    uint2 vB = __ldg(reinterpret_cast<const uint2*>(&g_h2h[(size_t)sB * D2 + lane * 4]));
    for (int i = 0; i < deg; i++) {
        int j = min(i + 2, deg - 1);
        int sC = g_col[b + j];
        float aC = g_asrc2[sC];
        uint2 vC = __ldg(reinterpret_cast<const uint2*>(&g_h2h[(size_t)sC * D2 + lane * 4]));
        float e = __expf(lrelu(aA + ad) - mx);
        den += e;
        const __half2* hp = reinterpret_cast<const __half2*>(&vA);
#pragma unroll
        for (int q = 0; q < 2; q++) {
            float2 f = __half22float2(hp[q]);
            acc[2 * q]     = fmaf(f.x, e, acc[2 * q]);
            acc[2 * q + 1] = fmaf(f.y, e, acc[2 * q + 1]);
        }
        aA = aB; vA = vB; aB = aC; vB = vC;
    }
    float inv = 1.f / (den + 1e-16f);
    float4 bb = __ldg(&reinterpret_cast<const float4*>(bias)[lane]);
    float4 o;
    o.x = elu(acc[0] * inv + bb.x); o.y = elu(acc[1] * inv + bb.y);
    o.z = elu(acc[2] * inv + bb.z); o.w = elu(acc[3] * inv + bb.w);
    reinterpret_cast<float4*>(&g_out2[(size_t)d * D2])[lane] = o;
}

// ---------------- pooling (batch sorted -> segmented accumulation) ---------
#define NPB 32
__global__ void pool_k(const int* __restrict__ batch) {
    int c = threadIdx.x;
    int n0 = blockIdx.x * NPB;
    int n1 = min(NN, n0 + NPB);
    if (n0 >= NN) return;
    int curg = batch[n0];
    float acc = 0.f, cnt = 0.f;
    for (int n = n0; n < n1; n++) {
        int gg = batch[n];
        if (gg != curg) {
            atomicAdd(&g_pool[curg * D2 + c], acc);
            if (c == 0) atomicAdd(&g_cnt[curg], cnt);
            acc = 0.f; cnt = 0.f; curg = gg;
        }
        acc += g_out2[(size_t)n * D2 + c];
        cnt += 1.f;
    }
    atomicAdd(&g_pool[curg * D2 + c], acc);
    if (c == 0) atomicAdd(&g_cnt[curg], cnt);
}

__global__ void final_k(const float* __restrict__ lin_w, const float* __restrict__ lin_b,
                        float* __restrict__ out) {
    int t = threadIdx.x;
    if (t >= NG * NCLS) return;
    int gph = t / NCLS, k = t - gph * NCLS;
    float inv = 1.f / fmaxf(g_cnt[gph], 1.f);
    float acc = 0.f;
    for (int c = 0; c < D2; c++)
        acc = fmaf(g_pool[gph * D2 + c] * inv, __ldg(&lin_w[c * NCLS + k]), acc);
    out[t] = acc + lin_b[k];
}

// ---------------- driver -----------------------------------------------------
#define SMEM_G1 ((64 * (FIN + 8) + FIN * (D1 + 8)) * 2)
#define SMEM_G2 ((128 * (D1 + 8) + 128 * (D2 + 8)) * 2)

extern "C" void kernel_launch(void* const* d_in, const int* in_sizes, int n_in,
                              void* d_out, int out_size) {
    const float* x        = (const float*)d_in[0];
    const int*   ei       = (const int*)d_in[1];
    const int*   batch    = (const int*)d_in[2];
    const float* W1       = (const float*)d_in[3];
    const float* att_src1 = (const float*)d_in[4];
    const float* att_dst1 = (const float*)d_in[5];
    const float* b1       = (const float*)d_in[6];
    const float* W2       = (const float*)d_in[7];
    const float* att_src2 = (const float*)d_in[8];
    const float* att_dst2 = (const float*)d_in[9];
    const float* b2       = (const float*)d_in[10];
    const float* lin_w    = (const float*)d_in[11];
    const float* lin_b    = (const float*)d_in[12];
    float* out = (float*)d_out;

    static cudaStream_t s1 = 0;
    static cudaEvent_t evRoot = 0, evCsr = 0, evEnd = 0;
    static int inited = 0;
    if (!inited) {
        cudaStreamCreateWithFlags(&s1, cudaStreamNonBlocking);
        cudaEventCreateWithFlags(&evRoot, cudaEventDisableTiming);
        cudaEventCreateWithFlags(&evCsr, cudaEventDisableTiming);
        cudaEventCreateWithFlags(&evEnd, cudaEventDisableTiming);
        cudaFuncSetAttribute((const void*)gemm_tc_k<FIN, D1, 64, 4, 2, NH1, false>,
                             cudaFuncAttributeMaxDynamicSharedMemorySize, SMEM_G1);
        cudaFuncSetAttribute((const void*)gemm_tc_k<D1, D2, 128, 8, 1, 1, true>,
                             cudaFuncAttributeMaxDynamicSharedMemorySize, SMEM_G2);
        inited = 1;
    }

    __half* h1p;    cudaGetSymbolAddress((void**)&h1p, g_h1h);
    __half* out1hp; cudaGetSymbolAddress((void**)&out1hp, g_out1h);
    __half* h2p;    cudaGetSymbolAddress((void**)&h2p, g_h2h);
    __half* w1hp;   cudaGetSymbolAddress((void**)&w1hp, g_w1h);
    __half* w2hp;   cudaGetSymbolAddress((void**)&w2hp, g_w2h);
    float*  as1p;   cudaGetSymbolAddress((void**)&as1p, g_asrc1);
    float*  ad1p;   cudaGetSymbolAddress((void**)&ad1p, g_adst1);
    float*  as2p;   cudaGetSymbolAddress((void**)&as2p, g_asrc2);
    float*  ad2p;   cudaGetSymbolAddress((void**)&ad2p, g_adst2);

    // fork: CSR build on s1 (deg assumed zeroed: module load / end-of-prev-replay)
    cudaEventRecord(evRoot, 0);
    cudaStreamWaitEvent(s1, evRoot, 0);
    deg_k<<<(EE / 8 + 255) / 256, 256, 0, s1>>>(ei);
    csum_k<<<(NCH + 63) / 64, 64, 0, s1>>>();
    scanc_k<<<1, 1024, 0, s1>>>();
    fill_k<<<(NCH + 63) / 64, 64, 0, s1>>>();
    scatter_k<<<(EE / 2 + 255) / 256, 256, 0, s1>>>(ei);
    cudaEventRecord(evCsr, s1);
    zdeg_k<<<(NN + 255) / 256, 256, 0, s1>>>();      // for next replay
    cudaEventRecord(evEnd, s1);

    convw_k<<<128, 256>>>(W1, W2);
    gemm_tc_k<FIN, D1, 64, 4, 2, NH1, false><<<(NN + 63) / 64, 256, SMEM_G1>>>(
        x, w1hp, h1p, att_src1, att_dst1, as1p, ad1p);

    // join: agg needs CSR
    cudaStreamWaitEvent(0, evCsr, 0);
    agg1_k<<<(NN * 32 + 255) / 256, 256>>>(b1);

    gemm_tc_k<D1, D2, 128, 8, 1, 1, true><<<(NN + 127) / 128, 256, SMEM_G2>>>(
        out1hp, w2hp, h2p, att_src2, att_dst2, as2p, ad2p);
    agg2_k<<<(NN * 32 + 255) / 256, 256>>>(b2);

    pool_k<<<(NN + NPB - 1) / NPB, D2>>>(batch);
    cudaStreamWaitEvent(0, evEnd, 0);                // join zdeg before graph end
    final_k<<<1, 256>>>(lin_w, lin_b, out);
}

// round 16
// speedup vs baseline: 2.7359x; 1.0655x over previous
#include <cuda_runtime.h>
#include <cuda_fp16.h>

#define NN 50000
#define EE 800000
#define ET 850000        // EE + NN self loops
#define FIN 128
#define D1 256           // H1*C1 = 4*64
#define C1C 64
#define NH1 4
#define D2 128
#define NG 32
#define NCLS 5
#define NEG_SLOPE 0.2f

// chunked scan
#define NCH 8192
#define CHW 7            // NCH*CHW = 57344 >= NN

// ---------------- scratch (static device globals; zero-init at module load) -
__device__ __half g_h1h[(size_t)NN * D1];
__device__ __half g_out1h[(size_t)NN * D1];
__device__ __half g_h2h[(size_t)NN * D2];
__device__ __half g_w1h[FIN * D1];
__device__ __half g_w2h[D1 * D2];
__device__ float  g_asrc1[NN * NH1], g_adst1[NN * NH1];
__device__ float  g_asrc2[NN], g_adst2[NN];
__device__ float  g_pool[NG * D2];
__device__ float  g_cnt[NG];
// CSR by destination (slot rowptr[d] holds the self loop)
__device__ int g_deg[NN];            // real-edge in-degree; re-zeroed at graph end
__device__ int g_rowptr[NN + 1];
__device__ int g_cursor[NN];
__device__ int g_col[ET];
__device__ int g_csum[NCH], g_cpre[NCH];

__device__ __forceinline__ float lrelu(float a) { return (a > 0.f) ? a : NEG_SLOPE * a; }
__device__ __forceinline__ float elu(float v)   { return (v > 0.f) ? v : expm1f(v); }
__device__ __forceinline__ unsigned sptr(const void* p) {
    return (unsigned)__cvta_generic_to_shared(p);
}

// ---------------- W conversion to fp16 --------------------------------------
__global__ void convw_k(const float* __restrict__ W1, const float* __restrict__ W2) {
    int i = blockIdx.x * blockDim.x + threadIdx.x;
    if (i < FIN * D1) g_w1h[i] = __float2half(W1[i]);
    if (i < D1 * D2)  g_w2h[i] = __float2half(W2[i]);
}

// ---------------- CSR build --------------------------------------------------
__global__ void deg_k(const int* __restrict__ ei) {
    int t = blockIdx.x * blockDim.x + threadIdx.x;
    int base = t * 8;
    if (base >= EE) return;
    int4 a = *reinterpret_cast<const int4*>(ei + EE + base);
    int4 b = *reinterpret_cast<const int4*>(ei + EE + base + 4);
    atomicAdd(&g_deg[a.x], 1); atomicAdd(&g_deg[a.y], 1);
    atomicAdd(&g_deg[a.z], 1); atomicAdd(&g_deg[a.w], 1);
    atomicAdd(&g_deg[b.x], 1); atomicAdd(&g_deg[b.y], 1);
    atomicAdd(&g_deg[b.z], 1); atomicAdd(&g_deg[b.w], 1);
}

// chunk partial sums (+ zero pool/cnt off the critical path)
__global__ void csum_k() {
    int t = blockIdx.x * blockDim.x + threadIdx.x;   // 0..NCH-1
    if (blockIdx.x == 0) {
        for (int i = threadIdx.x; i < NG * D2; i += blockDim.x) g_pool[i] = 0.f;
        if (threadIdx.x < NG) g_cnt[threadIdx.x] = 0.f;
    }
    if (t >= NCH) return;
    int base = t * CHW;
    int s = 0;
#pragma unroll
    for (int i = 0; i < CHW; i++) {
        int idx = base + i;
        if (idx < NN) s += g_deg[idx];
    }
    g_csum[t] = s;
}

// single-block scan over NCH=8192 chunk sums (8 per thread)
__global__ void scanc_k() {
    __shared__ int part[1024];
    int t = threadIdx.x;
    int c[8];
    int s = 0;
#pragma unroll
    for (int i = 0; i < 8; i++) { c[i] = g_csum[t * 8 + i]; s += c[i]; }
    part[t] = s;
    __syncthreads();
    for (int off = 1; off < 1024; off <<= 1) {
        int v = (t >= off) ? part[t - off] : 0;
        __syncthreads();
        part[t] += v;
        __syncthreads();
    }
    int run = part[t] - s;                 // exclusive prefix
#pragma unroll
    for (int i = 0; i < 8; i++) { g_cpre[t * 8 + i] = run; run += c[i]; }
    if (t == 0) g_rowptr[NN] = ET;
}

// fill rowptr/cursor/self-loops; rowptr[idx] = edge_prefix(idx) + idx
__global__ void fill_k() {
    int t = blockIdx.x * blockDim.x + threadIdx.x;   // 0..NCH-1
    if (t >= NCH) return;
    int base = t * CHW;
    int run = g_cpre[t];
#pragma unroll
    for (int i = 0; i < CHW; i++) {
        int idx = base + i;
        if (idx < NN) {
            int rp = run + idx;
            g_rowptr[idx] = rp;
            g_col[rp] = idx;               // self loop in slot 0
            g_cursor[idx] = rp + 1;
            run += g_deg[idx];
        }
    }
}

__global__ void scatter_k(const int* __restrict__ ei) {
    int t = blockIdx.x * blockDim.x + threadIdx.x;
    int e = t * 2;
    if (e >= EE) return;
    int2 s2 = *reinterpret_cast<const int2*>(ei + e);
    int2 d2 = *reinterpret_cast<const int2*>(ei + EE + e);
    int p0 = atomicAdd(&g_cursor[d2.x], 1);
    int p1 = atomicAdd(&g_cursor[d2.y], 1);
    g_col[p0] = s2.x;
    g_col[p1] = s2.y;
}

// zero deg for the next graph replay (off critical path)
__global__ void zdeg_k() {
    int i = blockIdx.x * blockDim.x + threadIdx.x;
    if (i < NN) g_deg[i] = 0;
}

// ---------------- tensor-core GEMM + fused attention scores ----------------
template <int KDIM, int NDIM, int MBLK, int MW, int NW, int HEADS, bool A_FP16>
__global__ void __launch_bounds__(MW * NW * 32)
gemm_tc_k(const void* __restrict__ Ain, const __half* __restrict__ Wh,
          __half* __restrict__ H,
          const float* __restrict__ att_s, const float* __restrict__ att_d,
          float* __restrict__ asrc, float* __restrict__ adst) {
    constexpr int AST = KDIM + 8;
    constexpr int WST = NDIM + 8;
    constexpr int KCH = (KDIM > 128) ? 128 : KDIM;
    constexpr int NTHR = MW * NW * 32;
    constexpr int NWP = NDIM / NW;
    constexpr int NFRAG = NWP / 8;
    constexpr int SPAN = NDIM / HEADS;
    constexpr int JPH = SPAN / 8;
    constexpr int HSLOTS = NWP / SPAN > 0 ? NWP / SPAN : 1;
    extern __shared__ __align__(16) __half smem[];
    __half* As = smem;
    __half* Ws = smem + MBLK * AST;
    int tid = threadIdx.x;
    int row0 = blockIdx.x * MBLK;

    for (int idx = tid; idx < MBLK * (KDIM / 8); idx += NTHR) {
        int m = idx / (KDIM / 8), kc = (idx % (KDIM / 8)) * 8;
        int r = row0 + m;
        uint4 pack = {0u, 0u, 0u, 0u};
        if (r < NN) {
            if (A_FP16) {
                pack = *reinterpret_cast<const uint4*>(
                    reinterpret_cast<const __half*>(Ain) + (size_t)r * KDIM + kc);
            } else {
                const float4* xp = reinterpret_cast<const float4*>(
                    reinterpret_cast<const float*>(Ain) + (size_t)r * KDIM + kc);
                float4 f0 = xp[0], f1 = xp[1];
                __half2 h0 = __floats2half2_rn(f0.x, f0.y);
                __half2 h1 = __floats2half2_rn(f0.z, f0.w);
                __half2 h2 = __floats2half2_rn(f1.x, f1.y);
                __half2 h3 = __floats2half2_rn(f1.z, f1.w);
                pack.x = *reinterpret_cast<unsigned*>(&h0);
                pack.y = *reinterpret_cast<unsigned*>(&h1);
                pack.z = *reinterpret_cast<unsigned*>(&h2);
                pack.w = *reinterpret_cast<unsigned*>(&h3);
            }
        }
        *reinterpret_cast<uint4*>(&As[m * AST + kc]) = pack;
    }

    int wid = tid >> 5, lane = tid & 31;
    int wm = wid % MW, wn = wid / MW;
    int mb = wm * 16, nb = wn * NWP;

    float acc[NFRAG][4];
#pragma unroll
    for (int j = 0; j < NFRAG; j++)
#pragma unroll
        for (int q = 0; q < 4; q++) acc[j][q] = 0.f;

    for (int kc = 0; kc < KDIM; kc += KCH) {
        if (kc) __syncthreads();
        for (int idx = tid; idx < KCH * (NDIM / 8); idx += NTHR) {
            int k = idx / (NDIM / 8), nc = (idx % (NDIM / 8)) * 8;
            *reinterpret_cast<uint4*>(&Ws[k * WST + nc]) =
                *reinterpret_cast<const uint4*>(&Wh[(size_t)(kc + k) * NDIM + nc]);
        }
        __syncthreads();

        for (int k0 = 0; k0 < KCH; k0 += 16) {
            unsigned a0, a1, a2, a3;
            unsigned aaddr = sptr(&As[(mb + (lane & 15)) * AST + kc + k0 + (lane >> 4) * 8]);
            asm volatile("ldmatrix.sync.aligned.m8n8.x4.shared.b16 {%0,%1,%2,%3}, [%4];"
                         : "=r"(a0), "=r"(a1), "=r"(a2), "=r"(a3) : "r"(aaddr));
#pragma unroll
            for (int j = 0; j < NFRAG; j++) {
                unsigned b0, b1;
                unsigned baddr = sptr(&Ws[(k0 + (lane & 15)) * WST + nb + j * 8]);
                asm volatile("ldmatrix.sync.aligned.m8n8.x2.trans.shared.b16 {%0,%1}, [%2];"
                             : "=r"(b0), "=r"(b1) : "r"(baddr));
                asm volatile("mma.sync.aligned.m16n8k16.row.col.f32.f16.f16.f32 "
                             "{%0,%1,%2,%3}, {%4,%5,%6,%7}, {%8,%9}, {%0,%1,%2,%3};"
                             : "+f"(acc[j][0]), "+f"(acc[j][1]), "+f"(acc[j][2]), "+f"(acc[j][3])
                             : "r"(a0), "r"(a1), "r"(a2), "r"(a3), "r"(b0), "r"(b1));
            }
        }
    }

    float sS[2][HSLOTS], sD[2][HSLOTS];
#pragma unroll
    for (int r = 0; r < 2; r++)
#pragma unroll
        for (int hs = 0; hs < HSLOTS; hs++) { sS[r][hs] = 0.f; sD[r][hs] = 0.f; }
    int rg0 = row0 + mb + (lane >> 2);
#pragma unroll
    for (int j = 0; j < NFRAG; j++) {
        int c0 = nb + j * 8 + (lane & 3) * 2;
        float as0 = __ldg(&att_s[c0]), as1 = __ldg(&att_s[c0 + 1]);
        float ad0 = __ldg(&att_d[c0]), ad1 = __ldg(&att_d[c0 + 1]);
        int slot = j / JPH;
        sS[0][slot] += acc[j][0] * as0 + acc[j][1] * as1;
        sS[1][slot] += acc[j][2] * as0 + acc[j][3] * as1;
        sD[0][slot] += acc[j][0] * ad0 + acc[j][1] * ad1;
        sD[1][slot] += acc[j][2] * ad0 + acc[j][3] * ad1;
        if (rg0 < NN) {
            __half2 hv = __floats2half2_rn(acc[j][0], acc[j][1]);
            *reinterpret_cast<__half2*>(&H[(size_t)rg0 * NDIM + c0]) = hv;
        }
        if (rg0 + 8 < NN) {
            __half2 hv = __floats2half2_rn(acc[j][2], acc[j][3]);
            *reinterpret_cast<__half2*>(&H[(size_t)(rg0 + 8) * NDIM + c0]) = hv;
        }
    }
#pragma unroll
    for (int r = 0; r < 2; r++)
#pragma unroll
        for (int hs = 0; hs < HSLOTS; hs++) {
            sS[r][hs] += __shfl_xor_sync(0xffffffffu, sS[r][hs], 1);
            sS[r][hs] += __shfl_xor_sync(0xffffffffu, sS[r][hs], 2);
            sD[r][hs] += __shfl_xor_sync(0xffffffffu, sD[r][hs], 1);
            sD[r][hs] += __shfl_xor_sync(0xffffffffu, sD[r][hs], 2);
        }
    if ((lane & 3) == 0) {
        int hbase = nb / SPAN;
#pragma unroll
        for (int hs = 0; hs < HSLOTS; hs++) {
            int h = hbase + hs;
            if (rg0 < NN) {
                asrc[rg0 * HEADS + h] = sS[0][hs];
                adst[rg0 * HEADS + h] = sD[0][hs];
            }
            if (rg0 + 8 < NN) {
                asrc[(rg0 + 8) * HEADS + h] = sS[1][hs];
                adst[(rg0 + 8) * HEADS + h] = sD[1][hs];
            }
        }
    }
}

// ---------------- fused softmax + aggregation (no max pass; scores are O(1),
// exp(a)/sum(exp(a)) == exp(a-mx)/sum(exp(a-mx)) mathematically) -------------
__global__ void agg1_k(const float* __restrict__ bias) {
    int g = blockIdx.x * blockDim.x + threadIdx.x;
    int d = g >> 5, lane = g & 31;
    if (d >= NN) return;
    int b = g_rowptr[d];
    int deg = g_rowptr[d + 1] - b;
    int h = lane >> 3;
    float adS = g_adst1[d * NH1 + h];
    float den = 0.f;
    float acc[8];
#pragma unroll
    for (int q = 0; q < 8; q++) acc[q] = 0.f;

    // depth-3 software pipeline
    int sA = g_col[b];
    int sB = g_col[b + min(1, deg - 1)];
    float aA = g_asrc1[sA * NH1 + h];
    float aB = g_asrc1[sB * NH1 + h];
    uint4 vA = __ldg(reinterpret_cast<const uint4*>(&g_h1h[(size_t)sA * D1 + lane * 8]));
    uint4 vB = __ldg(reinterpret_cast<const uint4*>(&g_h1h[(size_t)sB * D1 + lane * 8]));
    for (int i = 0; i < deg; i++) {
        int j = min(i + 2, deg - 1);
        int sC = g_col[b + j];
        float aC = g_asrc1[sC * NH1 + h];
        uint4 vC = __ldg(reinterpret_cast<const uint4*>(&g_h1h[(size_t)sC * D1 + lane * 8]));
        float e = __expf(lrelu(aA + adS));
        den += e;
        const __half2* hp = reinterpret_cast<const __half2*>(&vA);
#pragma unroll
        for (int q = 0; q < 4; q++) {
            float2 f = __half22float2(hp[q]);
            acc[2 * q]     = fmaf(f.x, e, acc[2 * q]);
            acc[2 * q + 1] = fmaf(f.y, e, acc[2 * q + 1]);
        }
        aA = aB; vA = vB; aB = aC; vB = vC;
    }
    float inv = 1.f / (den + 1e-16f);
    float4 b0 = __ldg(&reinterpret_cast<const float4*>(bias)[2 * lane]);
    float4 b1 = __ldg(&reinterpret_cast<const float4*>(bias)[2 * lane + 1]);
    float o0 = elu(acc[0] * inv + b0.x), o1 = elu(acc[1] * inv + b0.y);
    float o2 = elu(acc[2] * inv + b0.z), o3 = elu(acc[3] * inv + b0.w);
    float o4 = elu(acc[4] * inv + b1.x), o5 = elu(acc[5] * inv + b1.y);
    float o6 = elu(acc[6] * inv + b1.z), o7 = elu(acc[7] * inv + b1.w);
    __half2 p0 = __floats2half2_rn(o0, o1), p1 = __floats2half2_rn(o2, o3);
    __half2 p2 = __floats2half2_rn(o4, o5), p3 = __floats2half2_rn(o6, o7);
    uint4 pack;
    pack.x = *reinterpret_cast<unsigned*>(&p0);
    pack.y = *reinterpret_cast<unsigned*>(&p1);
    pack.z = *reinterpret_cast<unsigned*>(&p2);
    pack.w = *reinterpret_cast<unsigned*>(&p3);
    *reinterpret_cast<uint4*>(&g_out1h[(size_t)d * D1 + lane * 8]) = pack;
}

// layer2 agg + fused mean-pool accumulation (8 dst nodes per block)
__global__ void agg2_k(const float* __restrict__ bias, const int* __restrict__ batch) {
    __shared__ float sacc[D2];
    __shared__ float scnt;
    int wid = threadIdx.x >> 5, lane = threadIdx.x & 31;
    int d0 = blockIdx.x * 8;
    int d = d0 + wid;
    int nblk = min(8, NN - d0);
    int gFirst = batch[d0];
    int gLast = batch[d0 + nblk - 1];
    bool uniform = (gFirst == gLast);
    if (threadIdx.x < D2) sacc[threadIdx.x] = 0.f;
    if (threadIdx.x == 0) scnt = 0.f;
    __syncthreads();

    if (d < NN) {
        int b = g_rowptr[d];
        int deg = g_rowptr[d + 1] - b;
        float ad = g_adst2[d];
        float den = 0.f;
        float acc[4];
#pragma unroll
        for (int q = 0; q < 4; q++) acc[q] = 0.f;

        int sA = g_col[b];
        int sB = g_col[b + min(1, deg - 1)];
        float aA = g_asrc2[sA];
        float aB = g_asrc2[sB];
        uint2 vA = __ldg(reinterpret_cast<const uint2*>(&g_h2h[(size_t)sA * D2 + lane * 4]));
        uint2 vB = __ldg(reinterpret_cast<const uint2*>(&g_h2h[(size_t)sB * D2 + lane * 4]));
        for (int i = 0; i < deg; i++) {
            int j = min(i + 2, deg - 1);
            int sC = g_col[b + j];
            float aC = g_asrc2[sC];
            uint2 vC = __ldg(reinterpret_cast<const uint2*>(&g_h2h[(size_t)sC * D2 + lane * 4]));
            float e = __expf(lrelu(aA + ad));
            den += e;
            const __half2* hp = reinterpret_cast<const __half2*>(&vA);
#pragma unroll
            for (int q = 0; q < 2; q++) {
                float2 f = __half22float2(hp[q]);
                acc[2 * q]     = fmaf(f.x, e, acc[2 * q]);
                acc[2 * q + 1] = fmaf(f.y, e, acc[2 * q + 1]);
            }
            aA = aB; vA = vB; aB = aC; vB = vC;
        }
        float inv = 1.f / (den + 1e-16f);
        float4 bb = __ldg(&reinterpret_cast<const float4*>(bias)[lane]);
        float o0 = elu(acc[0] * inv + bb.x), o1 = elu(acc[1] * inv + bb.y);
        float o2 = elu(acc[2] * inv + bb.z), o3 = elu(acc[3] * inv + bb.w);
        if (uniform) {
            atomicAdd(&sacc[4 * lane + 0], o0);
            atomicAdd(&sacc[4 * lane + 1], o1);
            atomicAdd(&sacc[4 * lane + 2], o2);
            atomicAdd(&sacc[4 * lane + 3], o3);
            if (lane == 0) atomicAdd(&scnt, 1.f);
        } else {
            int gg = batch[d];
            atomicAdd(&g_pool[gg * D2 + 4 * lane + 0], o0);
            atomicAdd(&g_pool[gg * D2 + 4 * lane + 1], o1);
            atomicAdd(&g_pool[gg * D2 + 4 * lane + 2], o2);
            atomicAdd(&g_pool[gg * D2 + 4 * lane + 3], o3);
            if (lane == 0) atomicAdd(&g_cnt[gg], 1.f);
        }
    }
    __syncthreads();
    if (uniform) {
        if (threadIdx.x < D2) atomicAdd(&g_pool[gFirst * D2 + threadIdx.x], sacc[threadIdx.x]);
        if (threadIdx.x == 0) atomicAdd(&g_cnt[gFirst], scnt);
    }
}

__global__ void final_k(const float* __restrict__ lin_w, const float* __restrict__ lin_b,
                        float* __restrict__ out) {
    int t = threadIdx.x;
    if (t >= NG * NCLS) return;
    int gph = t / NCLS, k = t - gph * NCLS;
    float inv = 1.f / fmaxf(g_cnt[gph], 1.f);
    float acc = 0.f;
    for (int c = 0; c < D2; c++)
        acc = fmaf(g_pool[gph * D2 + c] * inv, __ldg(&lin_w[c * NCLS + k]), acc);
    out[t] = acc + lin_b[k];
}

// ---------------- driver -----------------------------------------------------
#define SMEM_G1 ((64 * (FIN + 8) + FIN * (D1 + 8)) * 2)
#define SMEM_G2 ((128 * (D1 + 8) + 128 * (D2 + 8)) * 2)

extern "C" void kernel_launch(void* const* d_in, const int* in_sizes, int n_in,
                              void* d_out, int out_size) {
    const float* x        = (const float*)d_in[0];
    const int*   ei       = (const int*)d_in[1];
    const int*   batch    = (const int*)d_in[2];
    const float* W1       = (const float*)d_in[3];
    const float* att_src1 = (const float*)d_in[4];
    const float* att_dst1 = (const float*)d_in[5];
    const float* b1       = (const float*)d_in[6];
    const float* W2       = (const float*)d_in[7];
    const float* att_src2 = (const float*)d_in[8];
    const float* att_dst2 = (const float*)d_in[9];
    const float* b2       = (const float*)d_in[10];
    const float* lin_w    = (const float*)d_in[11];
    const float* lin_b    = (const float*)d_in[12];
    float* out = (float*)d_out;

    static cudaStream_t s1 = 0;
    static cudaEvent_t evRoot = 0, evCsr = 0, evEnd = 0;
    static int inited = 0;
    if (!inited) {
        cudaStreamCreateWithFlags(&s1, cudaStreamNonBlocking);
        cudaEventCreateWithFlags(&evRoot, cudaEventDisableTiming);
        cudaEventCreateWithFlags(&evCsr, cudaEventDisableTiming);
        cudaEventCreateWithFlags(&evEnd, cudaEventDisableTiming);
        cudaFuncSetAttribute((const void*)gemm_tc_k<FIN, D1, 64, 4, 2, NH1, false>,
                             cudaFuncAttributeMaxDynamicSharedMemorySize, SMEM_G1);
        cudaFuncSetAttribute((const void*)gemm_tc_k<D1, D2, 128, 8, 1, 1, true>,
                             cudaFuncAttributeMaxDynamicSharedMemorySize, SMEM_G2);
        inited = 1;
    }

    __half* h1p;    cudaGetSymbolAddress((void**)&h1p, g_h1h);
    __half* out1hp; cudaGetSymbolAddress((void**)&out1hp, g_out1h);
    __half* h2p;    cudaGetSymbolAddress((void**)&h2p, g_h2h);
    __half* w1hp;   cudaGetSymbolAddress((void**)&w1hp, g_w1h);
    __half* w2hp;   cudaGetSymbolAddress((void**)&w2hp, g_w2h);
    float*  as1p;   cudaGetSymbolAddress((void**)&as1p, g_asrc1);
    float*  ad1p;   cudaGetSymbolAddress((void**)&ad1p, g_adst1);
    float*  as2p;   cudaGetSymbolAddress((void**)&as2p, g_asrc2);
    float*  ad2p;   cudaGetSymbolAddress((void**)&ad2p, g_adst2);

    // fork: CSR build on s1 (deg zeroed at module load / end of prev replay)
    cudaEventRecord(evRoot, 0);
    cudaStreamWaitEvent(s1, evRoot, 0);
    deg_k<<<(EE / 8 + 255) / 256, 256, 0, s1>>>(ei);
    csum_k<<<(NCH + 255) / 256, 256, 0, s1>>>();
    scanc_k<<<1, 1024, 0, s1>>>();
    fill_k<<<(NCH + 255) / 256, 256, 0, s1>>>();
    scatter_k<<<(EE / 2 + 255) / 256, 256, 0, s1>>>(ei);
    cudaEventRecord(evCsr, s1);
    zdeg_k<<<(NN + 255) / 256, 256, 0, s1>>>();      // for next replay
    cudaEventRecord(evEnd, s1);

    convw_k<<<128, 256>>>(W1, W2);
    gemm_tc_k<FIN, D1, 64, 4, 2, NH1, false><<<(NN + 63) / 64, 256, SMEM_G1>>>(
        x, w1hp, h1p, att_src1, att_dst1, as1p, ad1p);

    // join: agg needs CSR
    cudaStreamWaitEvent(0, evCsr, 0);
    agg1_k<<<(NN * 32 + 255) / 256, 256>>>(b1);

    gemm_tc_k<D1, D2, 128, 8, 1, 1, true><<<(NN + 127) / 128, 256, SMEM_G2>>>(
        out1hp, w2hp, h2p, att_src2, att_dst2, as2p, ad2p);
    agg2_k<<<(NN + 7) / 8, 256>>>(b2, batch);

    cudaStreamWaitEvent(0, evEnd, 0);                // join zdeg before graph end
    final_k<<<1, 256>>>(lin_w, lin_b, out);
}